// round 1
// baseline (speedup 1.0000x reference)
#include <cuda_runtime.h>
#include <math.h>

#define N_NODES 50000
#define IN_DIM  256
#define OUT_DIM 128
#define T_ROWS  4096
#define N_EDGES 262144
#define CAP     256          // per-row bucket capacity; P(overflow) ~ 1e-7 for Poisson(64)
#define LRELU_ALPHA 0.2f

// ---- scratch (static __device__ globals: allocation-free) ----
__device__ float g_h[(size_t)N_NODES * OUT_DIM];   // 25.6 MB
__device__ float g_s1[N_NODES];
__device__ float g_s2[N_NODES];
__device__ float g_e[N_EDGES];
__device__ int   g_cnt[T_ROWS];
__device__ int   g_bucket[T_ROWS * CAP];           // 4 MB
__device__ float g_hsum[OUT_DIM];
__device__ int   g_idx64;                          // 1 if adj/target are int64, 0 if int32

// -------------------------------------------------------------
// 0) zero counters + colsum accumulator, and sniff index dtype
// -------------------------------------------------------------
__global__ void init_kernel(const void* __restrict__ adj_raw) {
    int i = blockIdx.x * blockDim.x + threadIdx.x;
    if (i < T_ROWS) g_cnt[i] = 0;
    if (i >= T_ROWS && i < T_ROWS + OUT_DIM) g_hsum[i - T_ROWS] = 0.0f;

    // dtype sniff: view first 8192 int32 words. If data is int64 with values in
    // [0, 50000), every odd word is 0. If int32, odd words are random in [0,50000).
    if (blockIdx.x == 0) {
        const int* w = (const int*)adj_raw;
        int bad = 0;
        for (int j = threadIdx.x * 2 + 1; j < 8192; j += blockDim.x * 2)
            if (w[j] != 0) bad = 1;
        // reduce via shared
        __shared__ int sbad;
        if (threadIdx.x == 0) sbad = 0;
        __syncthreads();
        if (bad) atomicOr(&sbad, 1);
        __syncthreads();
        if (threadIdx.x == 0) g_idx64 = (sbad == 0) ? 1 : 0;
    }
}

// -------------------------------------------------------------
// 1) h = F @ W (fp32), fused s1 = h.a[:128], s2 = h.a[128:]
//    tile: 32 rows x 128 cols per 256-thread block, 4x4 per thread
// -------------------------------------------------------------
__global__ void __launch_bounds__(256) gemm_kernel(const float* __restrict__ F,
                                                   const float* __restrict__ W,
                                                   const float* __restrict__ a) {
    __shared__ float fs[32 * IN_DIM];                 // 32 KB
    const int row0 = blockIdx.x * 32;

    // cooperative tile load (tile is a contiguous region of F)
    {
        const float4* src = (const float4*)(F + (size_t)row0 * IN_DIM);
        float4* dst = (float4*)fs;
        const int nvalid4 = (min(32, N_NODES - row0)) * (IN_DIM / 4);
        for (int i = threadIdx.x; i < 32 * IN_DIM / 4; i += 256) {
            float4 v = make_float4(0.f, 0.f, 0.f, 0.f);
            if (i < nvalid4) v = src[i];
            dst[i] = v;
        }
    }
    __syncthreads();

    const int c  = threadIdx.x & 31;     // column quad -> cols 4c..4c+3
    const int r4 = (threadIdx.x >> 5) * 4; // rows r4..r4+3 (warp-uniform)

    float acc[4][4] = {};
    #pragma unroll 4
    for (int k = 0; k < IN_DIM; ++k) {
        const float4 w = __ldg(reinterpret_cast<const float4*>(W + k * OUT_DIM + (c << 2)));
        float f[4];
        #pragma unroll
        for (int i = 0; i < 4; ++i) f[i] = fs[(r4 + i) * IN_DIM + k];  // smem broadcast
        #pragma unroll
        for (int i = 0; i < 4; ++i) {
            acc[i][0] += f[i] * w.x;
            acc[i][1] += f[i] * w.y;
            acc[i][2] += f[i] * w.z;
            acc[i][3] += f[i] * w.w;
        }
    }

    float a1v[4], a2v[4];
    #pragma unroll
    for (int q = 0; q < 4; ++q) {
        a1v[q] = __ldg(a + (c << 2) + q);
        a2v[q] = __ldg(a + OUT_DIM + (c << 2) + q);
    }

    #pragma unroll
    for (int i = 0; i < 4; ++i) {
        const int row = row0 + r4 + i;             // warp-uniform
        if (row < N_NODES) {
            *reinterpret_cast<float4*>(&g_h[(size_t)row * OUT_DIM + (c << 2)]) =
                make_float4(acc[i][0], acc[i][1], acc[i][2], acc[i][3]);
            float p1 = acc[i][0]*a1v[0] + acc[i][1]*a1v[1] + acc[i][2]*a1v[2] + acc[i][3]*a1v[3];
            float p2 = acc[i][0]*a2v[0] + acc[i][1]*a2v[1] + acc[i][2]*a2v[2] + acc[i][3]*a2v[3];
            #pragma unroll
            for (int off = 16; off; off >>= 1) {
                p1 += __shfl_down_sync(0xffffffffu, p1, off);
                p2 += __shfl_down_sync(0xffffffffu, p2, off);
            }
            if (c == 0) { g_s1[row] = p1; g_s2[row] = p2; }
        }
    }
}

// -------------------------------------------------------------
// 2) column sums of h (for the all-empty-row softmax case)
// -------------------------------------------------------------
__global__ void hsum_kernel() {
    const int col = threadIdx.x & 127;
    const int sub = threadIdx.x >> 7;   // 0/1
    float s = 0.f;
    for (int row = blockIdx.x * 2 + sub; row < N_NODES; row += gridDim.x * 2)
        s += g_h[(size_t)row * OUT_DIM + col];
    __shared__ float red[256];
    red[threadIdx.x] = s;
    __syncthreads();
    if (threadIdx.x < 128)
        atomicAdd(&g_hsum[col], red[threadIdx.x] + red[threadIdx.x + 128]);
}

// -------------------------------------------------------------
// 3) per-edge score + bucket by target row
// -------------------------------------------------------------
__global__ void edge_kernel(const void* __restrict__ adj_raw,
                            const void* __restrict__ tgt_raw) {
    const int i = blockIdx.x * blockDim.x + threadIdx.x;
    if (i >= N_EDGES) return;
    const int is64 = g_idx64;
    int src, dstn, t;
    if (is64) {
        const long long* adj = (const long long*)adj_raw;
        const long long* tgt = (const long long*)tgt_raw;
        src  = (int)adj[i];
        dstn = (int)adj[N_EDGES + i];
        t    = (int)tgt[i];
    } else {
        const int* adj = (const int*)adj_raw;
        const int* tgt = (const int*)tgt_raw;
        src  = adj[i];
        dstn = adj[N_EDGES + i];
        t    = tgt[i];
    }
    float e = g_s1[src] + g_s2[dstn];
    e = (e > 0.f) ? e : LRELU_ALPHA * e;
    g_e[i] = e;
    const int pos = atomicAdd(&g_cnt[t], 1);
    if (pos < CAP) g_bucket[t * CAP + pos] = i;
}

// -------------------------------------------------------------
// 4) per-row: dedup (last edge wins) -> softmax -> weighted gather -> ELU
// -------------------------------------------------------------
__global__ void __launch_bounds__(128) row_kernel(const void* __restrict__ adj_raw,
                                                  float* __restrict__ out) {
    const int t   = blockIdx.x;
    const int tid = threadIdx.x;

    __shared__ int   sdst[CAP];
    __shared__ float se[CAP];
    __shared__ int   sidx[CAP];
    __shared__ float red[128];

    const int k = min(g_cnt[t], CAP);

    if (k == 0) {
        float v = g_hsum[tid] * (1.0f / (float)N_NODES);
        out[(size_t)t * OUT_DIM + tid] = (v > 0.f) ? v : expm1f(v);
        return;
    }

    const int is64 = g_idx64;
    for (int i = tid; i < k; i += 128) {
        const int e = g_bucket[t * CAP + i];
        sidx[i] = e;
        sdst[i] = is64 ? (int)((const long long*)adj_raw)[N_EDGES + e]
                       : ((const int*)adj_raw)[N_EDGES + e];
        se[i]   = g_e[e];
    }
    __syncthreads();

    // dedup: cell (t,dst) keeps the highest original edge index (last write wins)
    for (int i = tid; i < k; i += 128) {
        const int d = sdst[i], my = sidx[i];
        bool dead = false;
        for (int j = 0; j < k; ++j)
            if (sdst[j] == d && sidx[j] > my) { dead = true; break; }
        if (dead) se[i] = -3.0e38f;
    }
    __syncthreads();

    // row max
    float m = -3.0e38f;
    for (int i = tid; i < k; i += 128) m = fmaxf(m, se[i]);
    red[tid] = m;
    __syncthreads();
    #pragma unroll
    for (int s = 64; s; s >>= 1) { if (tid < s) red[tid] = fmaxf(red[tid], red[tid + s]); __syncthreads(); }
    m = red[0];
    __syncthreads();

    // exp + sum (dead entries underflow to exactly 0)
    float ssum = 0.f;
    for (int i = tid; i < k; i += 128) { float w = __expf(se[i] - m); se[i] = w; ssum += w; }
    __syncthreads();
    red[tid] = ssum;
    __syncthreads();
    #pragma unroll
    for (int s = 64; s; s >>= 1) { if (tid < s) red[tid] += red[tid + s]; __syncthreads(); }
    const float inv = 1.0f / red[0];
    __syncthreads();

    // weighted gather of h rows (coalesced 512B per row, mostly L2-resident)
    float acc = 0.f;
    #pragma unroll 4
    for (int i = 0; i < k; ++i)
        acc += se[i] * g_h[(size_t)sdst[i] * OUT_DIM + tid];

    const float v = acc * inv;
    out[(size_t)t * OUT_DIM + tid] = (v > 0.f) ? v : expm1f(v);
}

// -------------------------------------------------------------
extern "C" void kernel_launch(void* const* d_in, const int* in_sizes, int n_in,
                              void* d_out, int out_size) {
    const float* F   = (const float*)d_in[0];
    const void*  adj = d_in[1];
    const void*  tgt = d_in[2];
    const float* W   = (const float*)d_in[3];
    const float* a   = (const float*)d_in[4];
    float* out = (float*)d_out;

    init_kernel<<<17, 256>>>(adj);
    gemm_kernel<<<(N_NODES + 31) / 32, 256>>>(F, W, a);
    hsum_kernel<<<128, 256>>>();
    edge_kernel<<<(N_EDGES + 255) / 256, 256>>>(adj, tgt);
    row_kernel<<<T_ROWS, 128>>>(adj, out);
}

// round 3
// speedup vs baseline: 2.0122x; 2.0122x over previous
#include <cuda_runtime.h>
#include <cuda_bf16.h>
#include <math.h>
#include <stdint.h>

#define N_NODES 50000
#define IN_DIM  256
#define OUT_DIM 128
#define T_ROWS  4096
#define N_EDGES 262144
#define CAP     256
#define LRELU_ALPHA 0.2f
#define PAD 72   // bf16 elements per smem row (144B): conflict-free ldmatrix

// ---- scratch (static __device__ globals: allocation-free) ----
__device__ float g_h[(size_t)N_NODES * OUT_DIM];   // 25.6 MB
__device__ float g_s1[N_NODES];
__device__ float g_s2[N_NODES];
__device__ int   g_cnt[T_ROWS];
__device__ int   g_bucket[T_ROWS * CAP];
__device__ float g_hsum[OUT_DIM];
__device__ int   g_idx64;
__device__ int   g_anyempty;
// W^T pre-split: [128 n][256 k] bf16 hi/lo
__device__ __nv_bfloat16 g_WTh[OUT_DIM * IN_DIM];
__device__ __nv_bfloat16 g_WTl[OUT_DIM * IN_DIM];

// ---------------- helpers ----------------
__device__ __forceinline__ uint32_t smem_u32(const void* p) {
    uint32_t a;
    asm("{ .reg .u64 t; cvta.to.shared.u64 t, %1; cvt.u32.u64 %0, t; }" : "=r"(a) : "l"(p));
    return a;
}
__device__ __forceinline__ void ldmx4(uint32_t (&r)[4], uint32_t addr) {
    asm volatile("ldmatrix.sync.aligned.m8n8.x4.shared.b16 {%0,%1,%2,%3}, [%4];"
                 : "=r"(r[0]), "=r"(r[1]), "=r"(r[2]), "=r"(r[3]) : "r"(addr));
}
__device__ __forceinline__ void mma16816(float (&c)[4], const uint32_t (&a)[4],
                                         const uint32_t* b) {
    asm volatile("mma.sync.aligned.m16n8k16.row.col.f32.bf16.bf16.f32 "
                 "{%0,%1,%2,%3}, {%4,%5,%6,%7}, {%8,%9}, {%0,%1,%2,%3};"
                 : "+f"(c[0]), "+f"(c[1]), "+f"(c[2]), "+f"(c[3])
                 : "r"(a[0]), "r"(a[1]), "r"(a[2]), "r"(a[3]), "r"(b[0]), "r"(b[1]));
}

// SMEM layout (bytes) for gemm kernel
#define SM_AH   0
#define SM_AL   18432
#define SM_BH   36864
#define SM_BL   55296
#define SM_AVEC 73728     // 256 floats
#define SM_S1B  74752     // 128 floats
#define SM_S2B  75264
#define SMEM_TOTAL 75776

// =====================================================================
// 0) init + dtype sniff
// =====================================================================
__global__ void init_kernel(const void* __restrict__ adj_raw) {
    int i = blockIdx.x * blockDim.x + threadIdx.x;
    if (i < T_ROWS) g_cnt[i] = 0;
    if (i >= T_ROWS && i < T_ROWS + OUT_DIM) g_hsum[i - T_ROWS] = 0.0f;
    if (i == T_ROWS + OUT_DIM) g_anyempty = 0;

    if (blockIdx.x == 0) {
        const int* w = (const int*)adj_raw;
        int bad = 0;
        for (int j = threadIdx.x * 2 + 1; j < 8192; j += blockDim.x * 2)
            if (w[j] != 0) bad = 1;
        __shared__ int sbad;
        if (threadIdx.x == 0) sbad = 0;
        __syncthreads();
        if (bad) atomicOr(&sbad, 1);
        __syncthreads();
        if (threadIdx.x == 0) g_idx64 = (sbad == 0) ? 1 : 0;
    }
}

// =====================================================================
// 0b) W -> W^T bf16 hi/lo split
// =====================================================================
__global__ void wprep_kernel(const float* __restrict__ W) {
    int i = blockIdx.x * blockDim.x + threadIdx.x;
    if (i < IN_DIM * OUT_DIM) {
        int k = i >> 7, n = i & 127;
        float v = W[i];
        __nv_bfloat16 h = __float2bfloat16(v);
        __nv_bfloat16 l = __float2bfloat16(v - __bfloat162float(h));
        g_WTh[n * IN_DIM + k] = h;
        g_WTl[n * IN_DIM + k] = l;
    }
}

// =====================================================================
// 1) HMMA GEMM: h = F@W, bf16 3-pass split, fused s1/s2
//    block: 256 thr / 8 warps; tile 128x128x256; warp tile 64x32
// =====================================================================
__global__ void __launch_bounds__(256) gemm_mma_kernel(const float* __restrict__ F,
                                                       const float* __restrict__ a) {
    extern __shared__ char smem[];
    const uint32_t sb = smem_u32(smem);
    const int tid  = threadIdx.x;
    const int wid  = tid >> 5;
    const int lane = tid & 31;
    const int warp_m = wid & 1;   // 0..1 -> 64-row slab
    const int warp_n = wid >> 1;  // 0..3 -> 32-col slab
    const int row0 = blockIdx.x * 128;

    // stage a vector, zero s1/s2 partial buffers
    {
        float* avec = (float*)(smem + SM_AVEC);
        avec[tid] = __ldg(a + tid);
        if (tid < 128) {
            ((float*)(smem + SM_S1B))[tid] = 0.0f;
            ((float*)(smem + SM_S2B))[tid] = 0.0f;
        }
    }

    float acc[4][4][4];
    #pragma unroll
    for (int mt = 0; mt < 4; ++mt)
        #pragma unroll
        for (int nt = 0; nt < 4; ++nt)
            #pragma unroll
            for (int j = 0; j < 4; ++j) acc[mt][nt][j] = 0.0f;

    __nv_bfloat16* sAh = (__nv_bfloat16*)(smem + SM_AH);
    __nv_bfloat16* sAl = (__nv_bfloat16*)(smem + SM_AL);
    __nv_bfloat16* sBh = (__nv_bfloat16*)(smem + SM_BH);
    __nv_bfloat16* sBl = (__nv_bfloat16*)(smem + SM_BL);

    for (int c = 0; c < 4; ++c) {
        __syncthreads();   // protect smem reuse from previous chunk's compute

        // A chunk: rows [row0,row0+128), K cols [c*64, c*64+64), fp32 -> hi/lo bf16
        #pragma unroll
        for (int it = 0; it < 8; ++it) {
            const int lin = tid + 256 * it;     // 2048 float4s
            const int r = lin >> 4, j = lin & 15;
            float4 v = make_float4(0.f, 0.f, 0.f, 0.f);
            if (row0 + r < N_NODES)
                v = *reinterpret_cast<const float4*>(
                        F + (size_t)(row0 + r) * IN_DIM + c * 64 + j * 4);
            __nv_bfloat162 h01 = __floats2bfloat162_rn(v.x, v.y);
            __nv_bfloat162 h23 = __floats2bfloat162_rn(v.z, v.w);
            __nv_bfloat162 l01 = __floats2bfloat162_rn(v.x - __bfloat162float(h01.x),
                                                       v.y - __bfloat162float(h01.y));
            __nv_bfloat162 l23 = __floats2bfloat162_rn(v.z - __bfloat162float(h23.x),
                                                       v.w - __bfloat162float(h23.y));
            *(uint2*)&sAh[r * PAD + j * 4] = make_uint2(*(uint32_t*)&h01, *(uint32_t*)&h23);
            *(uint2*)&sAl[r * PAD + j * 4] = make_uint2(*(uint32_t*)&l01, *(uint32_t*)&l23);
        }
        // B chunk: W^T rows 0..127, K cols [c*64, +64), already bf16
        #pragma unroll
        for (int it = 0; it < 4; ++it) {
            const int lin = tid + 256 * it;     // 1024 uint4s
            const int n = lin >> 3, j = lin & 7;
            *(uint4*)&sBh[n * PAD + j * 8] =
                *(const uint4*)&g_WTh[n * IN_DIM + c * 64 + j * 8];
            *(uint4*)&sBl[n * PAD + j * 8] =
                *(const uint4*)&g_WTl[n * IN_DIM + c * 64 + j * 8];
        }
        __syncthreads();

        const int rs = lane & 7, q = lane >> 3;
        #pragma unroll
        for (int ks = 0; ks < 4; ++ks) {
            const int k0 = ks * 16;
            uint32_t ah[4][4], al[4][4];
            #pragma unroll
            for (int mt = 0; mt < 4; ++mt) {
                const int arow = warp_m * 64 + mt * 16 + rs + (q & 1) * 8;
                const int acol = k0 + (q >> 1) * 8;
                const uint32_t off = (uint32_t)(arow * PAD + acol) * 2;
                ldmx4(ah[mt], sb + SM_AH + off);
                ldmx4(al[mt], sb + SM_AL + off);
            }
            uint32_t bh[2][4], bl[2][4];
            #pragma unroll
            for (int np = 0; np < 2; ++np) {
                const int brow = warp_n * 32 + np * 16 + rs + (q >> 1) * 8;
                const int bcol = k0 + (q & 1) * 8;
                const uint32_t off = (uint32_t)(brow * PAD + bcol) * 2;
                ldmx4(bh[np], sb + SM_BH + off);
                ldmx4(bl[np], sb + SM_BL + off);
            }
            #pragma unroll
            for (int mt = 0; mt < 4; ++mt)
                #pragma unroll
                for (int nt = 0; nt < 4; ++nt) {
                    const uint32_t* bhp = &bh[nt >> 1][(nt & 1) * 2];
                    const uint32_t* blp = &bl[nt >> 1][(nt & 1) * 2];
                    mma16816(acc[mt][nt], ah[mt], bhp);   // Ah*Bh
                    mma16816(acc[mt][nt], ah[mt], blp);   // Ah*Bl
                    mma16816(acc[mt][nt], al[mt], bhp);   // Al*Bh
                }
        }
    }

    // epilogue: write h, fuse s1/s2
    const float* avec = (const float*)(smem + SM_AVEC);
    float* s1b = (float*)(smem + SM_S1B);
    float* s2b = (float*)(smem + SM_S2B);
    const int tg = lane & 3, gid = lane >> 2;

    #pragma unroll
    for (int mt = 0; mt < 4; ++mt)
        #pragma unroll
        for (int half = 0; half < 2; ++half) {
            const int rloc = warp_m * 64 + mt * 16 + half * 8 + gid;
            const int row  = row0 + rloc;
            float s1p = 0.f, s2p = 0.f;
            #pragma unroll
            for (int nt = 0; nt < 4; ++nt) {
                const float vx = acc[mt][nt][half * 2 + 0];
                const float vy = acc[mt][nt][half * 2 + 1];
                const int col = warp_n * 32 + nt * 8 + tg * 2;
                if (row < N_NODES)
                    *reinterpret_cast<float2*>(g_h + (size_t)row * OUT_DIM + col) =
                        make_float2(vx, vy);
                s1p += vx * avec[col]       + vy * avec[col + 1];
                s2p += vx * avec[128 + col] + vy * avec[128 + col + 1];
            }
            s1p += __shfl_xor_sync(0xffffffffu, s1p, 1);
            s1p += __shfl_xor_sync(0xffffffffu, s1p, 2);
            s2p += __shfl_xor_sync(0xffffffffu, s2p, 1);
            s2p += __shfl_xor_sync(0xffffffffu, s2p, 2);
            if (tg == 0) {
                atomicAdd(&s1b[rloc], s1p);
                atomicAdd(&s2b[rloc], s2p);
            }
        }
    __syncthreads();
    if (tid < 128 && row0 + tid < N_NODES) {
        g_s1[row0 + tid] = s1b[tid];
        g_s2[row0 + tid] = s2b[tid];
    }
}

// =====================================================================
// 2) per-edge bucketing (scores recomputed in row_kernel)
// =====================================================================
__global__ void edge_kernel(const void* __restrict__ tgt_raw) {
    const int i = blockIdx.x * blockDim.x + threadIdx.x;
    if (i >= N_EDGES) return;
    int t;
    if (g_idx64) t = (int)((const long long*)tgt_raw)[i];
    else         t = ((const int*)tgt_raw)[i];
    const int pos = atomicAdd(&g_cnt[t], 1);
    if (pos < CAP) g_bucket[t * CAP + pos] = i;
}

// =====================================================================
// 3) empty-row flag
// =====================================================================
__global__ void flag_kernel() {
    const int i = blockIdx.x * blockDim.x + threadIdx.x;
    if (i < T_ROWS && g_cnt[i] == 0) g_anyempty = 1;
}

// =====================================================================
// 4) column sums of h (only if some row is empty; else early exit)
// =====================================================================
__global__ void hsum_kernel() {
    if (!g_anyempty) return;
    const int col = threadIdx.x & 127;
    const int sub = threadIdx.x >> 7;
    float s = 0.f;
    for (int row = blockIdx.x * 2 + sub; row < N_NODES; row += gridDim.x * 2)
        s += g_h[(size_t)row * OUT_DIM + col];
    __shared__ float red[256];
    red[threadIdx.x] = s;
    __syncthreads();
    if (threadIdx.x < 128)
        atomicAdd(&g_hsum[col], red[threadIdx.x] + red[threadIdx.x + 128]);
}

// =====================================================================
// 5) per-row: score + dedup (last write wins) + softmax + gather + ELU
// =====================================================================
__global__ void __launch_bounds__(128) row_kernel(const void* __restrict__ adj_raw,
                                                  float* __restrict__ out) {
    const int t   = blockIdx.x;
    const int tid = threadIdx.x;

    __shared__ int   sdst[CAP];
    __shared__ float se[CAP];
    __shared__ int   sidx[CAP];
    __shared__ float red[128];

    const int k = min(g_cnt[t], CAP);

    if (k == 0) {
        float v = g_hsum[tid] * (1.0f / (float)N_NODES);
        out[(size_t)t * OUT_DIM + tid] = (v > 0.f) ? v : expm1f(v);
        return;
    }

    const int is64 = g_idx64;
    for (int i = tid; i < k; i += 128) {
        const int e = g_bucket[t * CAP + i];
        int src, dst;
        if (is64) {
            src = (int)((const long long*)adj_raw)[e];
            dst = (int)((const long long*)adj_raw)[N_EDGES + e];
        } else {
            src = ((const int*)adj_raw)[e];
            dst = ((const int*)adj_raw)[N_EDGES + e];
        }
        sidx[i] = e;
        sdst[i] = dst;
        float sc = g_s1[src] + g_s2[dst];
        se[i] = (sc > 0.f) ? sc : LRELU_ALPHA * sc;
    }
    __syncthreads();

    // dedup: cell (t,dst) keeps the highest original edge index
    for (int i = tid; i < k; i += 128) {
        const int d = sdst[i], my = sidx[i];
        bool dead = false;
        for (int j = 0; j < k; ++j)
            if (sdst[j] == d && sidx[j] > my) { dead = true; break; }
        if (dead) se[i] = -3.0e38f;
    }
    __syncthreads();

    float m = -3.0e38f;
    for (int i = tid; i < k; i += 128) m = fmaxf(m, se[i]);
    red[tid] = m;
    __syncthreads();
    #pragma unroll
    for (int s = 64; s; s >>= 1) { if (tid < s) red[tid] = fmaxf(red[tid], red[tid + s]); __syncthreads(); }
    m = red[0];
    __syncthreads();

    float ssum = 0.f;
    for (int i = tid; i < k; i += 128) { float w = __expf(se[i] - m); se[i] = w; ssum += w; }
    __syncthreads();
    red[tid] = ssum;
    __syncthreads();
    #pragma unroll
    for (int s = 64; s; s >>= 1) { if (tid < s) red[tid] += red[tid + s]; __syncthreads(); }
    const float inv = 1.0f / red[0];
    __syncthreads();

    float acc = 0.f;
    #pragma unroll 4
    for (int i = 0; i < k; ++i)
        acc += se[i] * g_h[(size_t)sdst[i] * OUT_DIM + tid];

    const float v = acc * inv;
    out[(size_t)t * OUT_DIM + tid] = (v > 0.f) ? v : expm1f(v);
}

// =====================================================================
extern "C" void kernel_launch(void* const* d_in, const int* in_sizes, int n_in,
                              void* d_out, int out_size) {
    const float* F   = (const float*)d_in[0];
    const void*  adj = d_in[1];
    const void*  tgt = d_in[2];
    const float* W   = (const float*)d_in[3];
    const float* a   = (const float*)d_in[4];
    float* out = (float*)d_out;

    static int smem_set = 0;
    if (!smem_set) {
        cudaFuncSetAttribute(gemm_mma_kernel,
                             cudaFuncAttributeMaxDynamicSharedMemorySize, SMEM_TOTAL);
        smem_set = 1;
    }

    init_kernel<<<17, 256>>>(adj);
    wprep_kernel<<<(IN_DIM * OUT_DIM + 255) / 256, 256>>>(W);
    gemm_mma_kernel<<<(N_NODES + 127) / 128, 256, SMEM_TOTAL>>>(F, a);
    edge_kernel<<<(N_EDGES + 255) / 256, 256>>>(tgt);
    flag_kernel<<<16, 256>>>();
    hsum_kernel<<<128, 256>>>();
    row_kernel<<<T_ROWS, 128>>>(adj, out);
}

// round 4
// speedup vs baseline: 2.0556x; 1.0216x over previous
#include <cuda_runtime.h>
#include <cuda_bf16.h>
#include <math.h>
#include <stdint.h>

#define N_NODES 50000
#define IN_DIM  256
#define OUT_DIM 128
#define T_ROWS  4096
#define N_EDGES 262144
#define CAP     256
#define LRELU_ALPHA 0.2f
#define PAD 72   // bf16 elements per smem row (144B): conflict-free ldmatrix

// ---- scratch (static __device__ globals: allocation-free) ----
__device__ float g_h[(size_t)N_NODES * OUT_DIM];   // 25.6 MB
__device__ float g_s1[N_NODES];
__device__ float g_s2[N_NODES];
__device__ int   g_cnt[T_ROWS];
__device__ int   g_bucket[T_ROWS * CAP];
__device__ float g_hsum[OUT_DIM];
__device__ int   g_idx64;
__device__ int   g_anyempty;
// W^T pre-split: [128 n][256 k] bf16 hi/lo
__device__ __nv_bfloat16 g_WTh[OUT_DIM * IN_DIM];
__device__ __nv_bfloat16 g_WTl[OUT_DIM * IN_DIM];

// ---------------- helpers ----------------
__device__ __forceinline__ uint32_t smem_u32(const void* p) {
    uint32_t a;
    asm("{ .reg .u64 t; cvta.to.shared.u64 t, %1; cvt.u32.u64 %0, t; }" : "=r"(a) : "l"(p));
    return a;
}
__device__ __forceinline__ void ldmx4(uint32_t (&r)[4], uint32_t addr) {
    asm volatile("ldmatrix.sync.aligned.m8n8.x4.shared.b16 {%0,%1,%2,%3}, [%4];"
                 : "=r"(r[0]), "=r"(r[1]), "=r"(r[2]), "=r"(r[3]) : "r"(addr));
}
__device__ __forceinline__ void mma16816(float (&c)[4], const uint32_t (&a)[4],
                                         const uint32_t* b) {
    asm volatile("mma.sync.aligned.m16n8k16.row.col.f32.bf16.bf16.f32 "
                 "{%0,%1,%2,%3}, {%4,%5,%6,%7}, {%8,%9}, {%0,%1,%2,%3};"
                 : "+f"(c[0]), "+f"(c[1]), "+f"(c[2]), "+f"(c[3])
                 : "r"(a[0]), "r"(a[1]), "r"(a[2]), "r"(a[3]), "r"(b[0]), "r"(b[1]));
}
__device__ __forceinline__ void cp16(uint32_t dst, const void* src) {
    asm volatile("cp.async.cg.shared.global [%0], [%1], 16;" :: "r"(dst), "l"(src) : "memory");
}
#define CP_COMMIT() asm volatile("cp.async.commit_group;" ::: "memory")
#define CP_WAIT1()  asm volatile("cp.async.wait_group 1;" ::: "memory")
#define CP_WAIT0()  asm volatile("cp.async.wait_group 0;" ::: "memory")

// SMEM layout (bytes) for gemm kernel
#define SM_AH    0                     // 18432
#define SM_AL    18432                 // 18432
#define SM_B0    36864                 // buf0: hi 18432 + lo 18432
#define SM_B1    73728                 // buf1: hi 18432 + lo 18432
#define SM_AVEC  110592                // 256 floats
#define SM_S1B   111616                // 128 floats
#define SM_S2B   112128
#define SMEM_TOTAL 112640
#define B_BUF_STRIDE 36864
#define B_LO_OFF 18432

// =====================================================================
// 0) prep: W split + counters + dtype sniff (one launch)
// =====================================================================
__global__ void prep_kernel(const float* __restrict__ W,
                            const void* __restrict__ adj_raw) {
    const int b = blockIdx.x;
    if (b < 128) {
        // W -> W^T bf16 hi/lo
        const int i = b * 256 + threadIdx.x;    // 0..32767
        const int k = i >> 7, n = i & 127;
        const float v = W[i];
        __nv_bfloat16 h = __float2bfloat16(v);
        __nv_bfloat16 l = __float2bfloat16(v - __bfloat162float(h));
        g_WTh[n * IN_DIM + k] = h;
        g_WTl[n * IN_DIM + k] = l;
    } else {
        const int i = (b - 128) * 256 + threadIdx.x;  // 0..4351
        if (i < T_ROWS) g_cnt[i] = 0;
        if (i >= T_ROWS && i < T_ROWS + OUT_DIM) g_hsum[i - T_ROWS] = 0.0f;
        if (i == T_ROWS + OUT_DIM) g_anyempty = 0;
        if (b == 143) {
            // dtype sniff on adj
            const int* w = (const int*)adj_raw;
            int bad = 0;
            for (int j = threadIdx.x * 2 + 1; j < 8192; j += 512)
                if (w[j] != 0) bad = 1;
            __shared__ int sbad;
            if (threadIdx.x == 0) sbad = 0;
            __syncthreads();
            if (bad) atomicOr(&sbad, 1);
            __syncthreads();
            if (threadIdx.x == 0) g_idx64 = (sbad == 0) ? 1 : 0;
        }
    }
}

// =====================================================================
// 1) HMMA GEMM: h = F@W, bf16 3-pass split, fused s1/s2
//    pipelined: reg-prefetch A, cp.async double-buffered B
// =====================================================================
__global__ void __launch_bounds__(256) gemm_mma_kernel(const float* __restrict__ F,
                                                       const float* __restrict__ a) {
    extern __shared__ char smem[];
    const uint32_t sb = smem_u32(smem);
    const int tid  = threadIdx.x;
    const int wid  = tid >> 5;
    const int lane = tid & 31;
    const int warp_m = wid & 1;
    const int warp_n = wid >> 1;
    const int row0 = blockIdx.x * 128;

    {
        float* avec = (float*)(smem + SM_AVEC);
        avec[tid] = __ldg(a + tid);
        if (tid < 128) {
            ((float*)(smem + SM_S1B))[tid] = 0.0f;
            ((float*)(smem + SM_S2B))[tid] = 0.0f;
        }
    }

    float acc[4][4][4];
    #pragma unroll
    for (int mt = 0; mt < 4; ++mt)
        #pragma unroll
        for (int nt = 0; nt < 4; ++nt)
            #pragma unroll
            for (int j = 0; j < 4; ++j) acc[mt][nt][j] = 0.0f;

    __nv_bfloat16* sAh = (__nv_bfloat16*)(smem + SM_AH);
    __nv_bfloat16* sAl = (__nv_bfloat16*)(smem + SM_AL);

    const int ar = (tid * 16) >> 4 >> 0;   // placeholder to keep indices clear below

    // ---- A prefetch (registers): chunk 0
    float4 pf[8];
    #pragma unroll
    for (int it = 0; it < 8; ++it) {
        const int lin = tid + 256 * it;
        const int r = lin >> 4, j = lin & 15;
        pf[it] = make_float4(0.f, 0.f, 0.f, 0.f);
        if (row0 + r < N_NODES)
            pf[it] = *reinterpret_cast<const float4*>(
                         F + (size_t)(row0 + r) * IN_DIM + 0 * 64 + j * 4);
    }
    // ---- B cp.async: chunk 0 -> buf 0  (8 x 16B per thread: 4 hi + 4 lo)
    {
        const uint32_t bbase = sb + SM_B0;
        #pragma unroll
        for (int it = 0; it < 4; ++it) {
            const int lin = tid + 256 * it;        // 1024 uint4s
            const int n = lin >> 3, j = lin & 7;
            cp16(bbase + (uint32_t)(n * PAD + j * 8) * 2,
                 &g_WTh[n * IN_DIM + 0 * 64 + j * 8]);
            cp16(bbase + B_LO_OFF + (uint32_t)(n * PAD + j * 8) * 2,
                 &g_WTl[n * IN_DIM + 0 * 64 + j * 8]);
        }
        CP_COMMIT();
    }

    for (int c = 0; c < 4; ++c) {
        __syncthreads();   // A smem free from previous compute

        // store prefetched A chunk with hi/lo conversion
        #pragma unroll
        for (int it = 0; it < 8; ++it) {
            const int lin = tid + 256 * it;
            const int r = lin >> 4, j = lin & 15;
            const float4 v = pf[it];
            __nv_bfloat162 h01 = __floats2bfloat162_rn(v.x, v.y);
            __nv_bfloat162 h23 = __floats2bfloat162_rn(v.z, v.w);
            __nv_bfloat162 l01 = __floats2bfloat162_rn(v.x - __bfloat162float(h01.x),
                                                       v.y - __bfloat162float(h01.y));
            __nv_bfloat162 l23 = __floats2bfloat162_rn(v.z - __bfloat162float(h23.x),
                                                       v.w - __bfloat162float(h23.y));
            *(uint2*)&sAh[r * PAD + j * 4] = make_uint2(*(uint32_t*)&h01, *(uint32_t*)&h23);
            *(uint2*)&sAl[r * PAD + j * 4] = make_uint2(*(uint32_t*)&l01, *(uint32_t*)&l23);
        }

        // kick off next B chunk into alternate buffer
        if (c < 3) {
            const uint32_t bbase = sb + SM_B0 + ((c + 1) & 1) * B_BUF_STRIDE;
            #pragma unroll
            for (int it = 0; it < 4; ++it) {
                const int lin = tid + 256 * it;
                const int n = lin >> 3, j = lin & 7;
                cp16(bbase + (uint32_t)(n * PAD + j * 8) * 2,
                     &g_WTh[n * IN_DIM + (c + 1) * 64 + j * 8]);
                cp16(bbase + B_LO_OFF + (uint32_t)(n * PAD + j * 8) * 2,
                     &g_WTl[n * IN_DIM + (c + 1) * 64 + j * 8]);
            }
            CP_COMMIT();
            CP_WAIT1();          // chunk c's group complete
        } else {
            CP_WAIT0();
        }
        __syncthreads();

        // prefetch next A chunk (LDGs overlap the MMA section below)
        if (c < 3) {
            #pragma unroll
            for (int it = 0; it < 8; ++it) {
                const int lin = tid + 256 * it;
                const int r = lin >> 4, j = lin & 15;
                pf[it] = make_float4(0.f, 0.f, 0.f, 0.f);
                if (row0 + r < N_NODES)
                    pf[it] = *reinterpret_cast<const float4*>(
                                 F + (size_t)(row0 + r) * IN_DIM + (c + 1) * 64 + j * 4);
            }
        }

        // ---- compute chunk c
        const uint32_t bh_off = SM_B0 + (c & 1) * B_BUF_STRIDE;
        const uint32_t bl_off = bh_off + B_LO_OFF;
        const int rs = lane & 7, q = lane >> 3;
        #pragma unroll
        for (int ks = 0; ks < 4; ++ks) {
            const int k0 = ks * 16;
            uint32_t ah[4][4], al[4][4];
            #pragma unroll
            for (int mt = 0; mt < 4; ++mt) {
                const int arow = warp_m * 64 + mt * 16 + rs + (q & 1) * 8;
                const int acol = k0 + (q >> 1) * 8;
                const uint32_t off = (uint32_t)(arow * PAD + acol) * 2;
                ldmx4(ah[mt], sb + SM_AH + off);
                ldmx4(al[mt], sb + SM_AL + off);
            }
            uint32_t bh[2][4], bl[2][4];
            #pragma unroll
            for (int np = 0; np < 2; ++np) {
                const int brow = warp_n * 32 + np * 16 + rs + (q >> 1) * 8;
                const int bcol = k0 + (q & 1) * 8;
                const uint32_t off = (uint32_t)(brow * PAD + bcol) * 2;
                ldmx4(bh[np], sb + bh_off + off);
                ldmx4(bl[np], sb + bl_off + off);
            }
            #pragma unroll
            for (int mt = 0; mt < 4; ++mt)
                #pragma unroll
                for (int nt = 0; nt < 4; ++nt) {
                    const uint32_t* bhp = &bh[nt >> 1][(nt & 1) * 2];
                    const uint32_t* blp = &bl[nt >> 1][(nt & 1) * 2];
                    mma16816(acc[mt][nt], ah[mt], bhp);   // Ah*Bh
                    mma16816(acc[mt][nt], ah[mt], blp);   // Ah*Bl
                    mma16816(acc[mt][nt], al[mt], bhp);   // Al*Bh
                }
        }
    }

    // epilogue: write h, fuse s1/s2
    const float* avec = (const float*)(smem + SM_AVEC);
    float* s1b = (float*)(smem + SM_S1B);
    float* s2b = (float*)(smem + SM_S2B);
    const int tg = lane & 3, gid = lane >> 2;

    #pragma unroll
    for (int mt = 0; mt < 4; ++mt)
        #pragma unroll
        for (int half = 0; half < 2; ++half) {
            const int rloc = warp_m * 64 + mt * 16 + half * 8 + gid;
            const int row  = row0 + rloc;
            float s1p = 0.f, s2p = 0.f;
            #pragma unroll
            for (int nt = 0; nt < 4; ++nt) {
                const float vx = acc[mt][nt][half * 2 + 0];
                const float vy = acc[mt][nt][half * 2 + 1];
                const int col = warp_n * 32 + nt * 8 + tg * 2;
                if (row < N_NODES)
                    *reinterpret_cast<float2*>(g_h + (size_t)row * OUT_DIM + col) =
                        make_float2(vx, vy);
                s1p += vx * avec[col]       + vy * avec[col + 1];
                s2p += vx * avec[128 + col] + vy * avec[128 + col + 1];
            }
            s1p += __shfl_xor_sync(0xffffffffu, s1p, 1);
            s1p += __shfl_xor_sync(0xffffffffu, s1p, 2);
            s2p += __shfl_xor_sync(0xffffffffu, s2p, 1);
            s2p += __shfl_xor_sync(0xffffffffu, s2p, 2);
            if (tg == 0) {
                atomicAdd(&s1b[rloc], s1p);
                atomicAdd(&s2b[rloc], s2p);
            }
        }
    __syncthreads();
    if (tid < 128 && row0 + tid < N_NODES) {
        g_s1[row0 + tid] = s1b[tid];
        g_s2[row0 + tid] = s2b[tid];
    }
}

// =====================================================================
// 2) per-edge bucketing: 4 edges/thread, batched for MLP
// =====================================================================
__global__ void __launch_bounds__(256) edge_kernel(const void* __restrict__ tgt_raw) {
    const int base = blockIdx.x * 256 + threadIdx.x;   // grid 256 -> 65536 threads
    const int is64 = g_idx64;
    int t[4];
    #pragma unroll
    for (int u = 0; u < 4; ++u) {
        const int i = base + u * 65536;
        t[u] = is64 ? (int)((const long long*)tgt_raw)[i]
                    : ((const int*)tgt_raw)[i];
    }
    int p[4];
    #pragma unroll
    for (int u = 0; u < 4; ++u) p[u] = atomicAdd(&g_cnt[t[u]], 1);
    #pragma unroll
    for (int u = 0; u < 4; ++u)
        if (p[u] < CAP) g_bucket[t[u] * CAP + p[u]] = base + u * 65536;
}

// =====================================================================
// 3) empty-row flag
// =====================================================================
__global__ void flag_kernel() {
    const int i = blockIdx.x * blockDim.x + threadIdx.x;
    if (i < T_ROWS && g_cnt[i] == 0) g_anyempty = 1;
}

// =====================================================================
// 4) column sums of h (only if some row is empty; else early exit)
// =====================================================================
__global__ void hsum_kernel() {
    if (!g_anyempty) return;
    const int col = threadIdx.x & 127;
    const int sub = threadIdx.x >> 7;
    float s = 0.f;
    for (int row = blockIdx.x * 2 + sub; row < N_NODES; row += gridDim.x * 2)
        s += g_h[(size_t)row * OUT_DIM + col];
    __shared__ float red[256];
    red[threadIdx.x] = s;
    __syncthreads();
    if (threadIdx.x < 128)
        atomicAdd(&g_hsum[col], red[threadIdx.x] + red[threadIdx.x + 128]);
}

// =====================================================================
// 5) per-row: score + dedup (last write wins) + softmax + gather + ELU
// =====================================================================
__global__ void __launch_bounds__(128) row_kernel(const void* __restrict__ adj_raw,
                                                  float* __restrict__ out) {
    const int t   = blockIdx.x;
    const int tid = threadIdx.x;

    __shared__ int   sdst[CAP];
    __shared__ float se[CAP];
    __shared__ int   sidx[CAP];
    __shared__ float red[128];

    const int k = min(g_cnt[t], CAP);

    if (k == 0) {
        float v = g_hsum[tid] * (1.0f / (float)N_NODES);
        out[(size_t)t * OUT_DIM + tid] = (v > 0.f) ? v : expm1f(v);
        return;
    }

    const int is64 = g_idx64;
    for (int i = tid; i < k; i += 128) {
        const int e = g_bucket[t * CAP + i];
        int src, dst;
        if (is64) {
            src = (int)((const long long*)adj_raw)[e];
            dst = (int)((const long long*)adj_raw)[N_EDGES + e];
        } else {
            src = ((const int*)adj_raw)[e];
            dst = ((const int*)adj_raw)[N_EDGES + e];
        }
        sidx[i] = e;
        sdst[i] = dst;
        float sc = g_s1[src] + g_s2[dst];
        se[i] = (sc > 0.f) ? sc : LRELU_ALPHA * sc;
    }
    __syncthreads();

    // dedup: cell (t,dst) keeps the highest original edge index
    for (int i = tid; i < k; i += 128) {
        const int d = sdst[i], my = sidx[i];
        bool dead = false;
        for (int j = 0; j < k; ++j)
            if (sdst[j] == d && sidx[j] > my) { dead = true; break; }
        if (dead) se[i] = -3.0e38f;
    }
    __syncthreads();

    float m = -3.0e38f;
    for (int i = tid; i < k; i += 128) m = fmaxf(m, se[i]);
    red[tid] = m;
    __syncthreads();
    #pragma unroll
    for (int s = 64; s; s >>= 1) { if (tid < s) red[tid] = fmaxf(red[tid], red[tid + s]); __syncthreads(); }
    m = red[0];
    __syncthreads();

    float ssum = 0.f;
    for (int i = tid; i < k; i += 128) { float w = __expf(se[i] - m); se[i] = w; ssum += w; }
    __syncthreads();
    red[tid] = ssum;
    __syncthreads();
    #pragma unroll
    for (int s = 64; s; s >>= 1) { if (tid < s) red[tid] += red[tid + s]; __syncthreads(); }
    const float inv = 1.0f / red[0];
    __syncthreads();

    float acc = 0.f;
    #pragma unroll 4
    for (int i = 0; i < k; ++i)
        acc += se[i] * g_h[(size_t)sdst[i] * OUT_DIM + tid];

    const float v = acc * inv;
    out[(size_t)t * OUT_DIM + tid] = (v > 0.f) ? v : expm1f(v);
}

// =====================================================================
extern "C" void kernel_launch(void* const* d_in, const int* in_sizes, int n_in,
                              void* d_out, int out_size) {
    const float* F   = (const float*)d_in[0];
    const void*  adj = d_in[1];
    const void*  tgt = d_in[2];
    const float* W   = (const float*)d_in[3];
    const float* a   = (const float*)d_in[4];
    float* out = (float*)d_out;

    static int smem_set = 0;
    if (!smem_set) {
        cudaFuncSetAttribute(gemm_mma_kernel,
                             cudaFuncAttributeMaxDynamicSharedMemorySize, SMEM_TOTAL);
        smem_set = 1;
    }

    prep_kernel<<<145, 256>>>(W, adj);
    gemm_mma_kernel<<<(N_NODES + 127) / 128, 256, SMEM_TOTAL>>>(F, a);
    edge_kernel<<<256, 256>>>(tgt);
    flag_kernel<<<16, 256>>>();
    hsum_kernel<<<128, 256>>>();
    row_kernel<<<T_ROWS, 128>>>(adj, out);
}

// round 5
// speedup vs baseline: 2.3252x; 1.1311x over previous
#include <cuda_runtime.h>
#include <cuda_bf16.h>
#include <math.h>
#include <stdint.h>

#define N_NODES 50000
#define IN_DIM  256
#define OUT_DIM 128
#define T_ROWS  4096
#define N_EDGES 262144
#define CAP     256
#define LRELU_ALPHA 0.2f
#define PAD 72   // bf16 elements per smem row (144B): conflict-free ldmatrix

// ---- scratch (static __device__ globals: allocation-free) ----
__device__ float g_h[(size_t)N_NODES * OUT_DIM];   // 25.6 MB
__device__ float g_s1[N_NODES];
__device__ float g_s2[N_NODES];
__device__ int   g_cnt[T_ROWS];
__device__ int   g_bucket[T_ROWS * CAP];
__device__ int   g_idx64;
// W^T pre-split: [128 n][256 k] bf16 hi/lo
__device__ __nv_bfloat16 g_WTh[OUT_DIM * IN_DIM];
__device__ __nv_bfloat16 g_WTl[OUT_DIM * IN_DIM];

// ---------------- helpers ----------------
__device__ __forceinline__ uint32_t smem_u32(const void* p) {
    uint32_t a;
    asm("{ .reg .u64 t; cvta.to.shared.u64 t, %1; cvt.u32.u64 %0, t; }" : "=r"(a) : "l"(p));
    return a;
}
__device__ __forceinline__ void ldmx4(uint32_t (&r)[4], uint32_t addr) {
    asm volatile("ldmatrix.sync.aligned.m8n8.x4.shared.b16 {%0,%1,%2,%3}, [%4];"
                 : "=r"(r[0]), "=r"(r[1]), "=r"(r[2]), "=r"(r[3]) : "r"(addr));
}
__device__ __forceinline__ void mma16816(float (&c)[4], const uint32_t (&a)[4],
                                         const uint32_t* b) {
    asm volatile("mma.sync.aligned.m16n8k16.row.col.f32.bf16.bf16.f32 "
                 "{%0,%1,%2,%3}, {%4,%5,%6,%7}, {%8,%9}, {%0,%1,%2,%3};"
                 : "+f"(c[0]), "+f"(c[1]), "+f"(c[2]), "+f"(c[3])
                 : "r"(a[0]), "r"(a[1]), "r"(a[2]), "r"(a[3]), "r"(b[0]), "r"(b[1]));
}
__device__ __forceinline__ void cp16(uint32_t dst, const void* src) {
    asm volatile("cp.async.cg.shared.global [%0], [%1], 16;" :: "r"(dst), "l"(src) : "memory");
}
#define CP_COMMIT() asm volatile("cp.async.commit_group;" ::: "memory")
#define CP_WAIT1()  asm volatile("cp.async.wait_group 1;" ::: "memory")
#define CP_WAIT0()  asm volatile("cp.async.wait_group 0;" ::: "memory")

// SMEM layout (bytes) for gemm kernel
#define SM_AH    0                     // 18432
#define SM_AL    18432                 // 18432
#define SM_B0    36864                 // buf0: hi 18432 + lo 18432
#define SM_B1    73728                 // buf1: hi 18432 + lo 18432
#define SM_AVEC  110592                // 256 floats
#define SM_S1B   111616                // 128 floats
#define SM_S2B   112128
#define SMEM_TOTAL 112640
#define B_BUF_STRIDE 36864
#define B_LO_OFF 18432

// =====================================================================
// 0) prep: W split + counters + dtype sniff (one launch)
// =====================================================================
__global__ void prep_kernel(const float* __restrict__ W,
                            const void* __restrict__ adj_raw) {
    const int b = blockIdx.x;
    if (b < 128) {
        // W -> W^T bf16 hi/lo
        const int i = b * 256 + threadIdx.x;    // 0..32767
        const int k = i >> 7, n = i & 127;
        const float v = W[i];
        __nv_bfloat16 h = __float2bfloat16(v);
        __nv_bfloat16 l = __float2bfloat16(v - __bfloat162float(h));
        g_WTh[n * IN_DIM + k] = h;
        g_WTl[n * IN_DIM + k] = l;
    } else {
        const int i = (b - 128) * 256 + threadIdx.x;  // 0..4351
        if (i < T_ROWS) g_cnt[i] = 0;
        if (b == 144) {
            // dtype sniff on adj
            const int* w = (const int*)adj_raw;
            int bad = 0;
            for (int j = threadIdx.x * 2 + 1; j < 8192; j += 512)
                if (w[j] != 0) bad = 1;
            __shared__ int sbad;
            if (threadIdx.x == 0) sbad = 0;
            __syncthreads();
            if (bad) atomicOr(&sbad, 1);
            __syncthreads();
            if (threadIdx.x == 0) g_idx64 = (sbad == 0) ? 1 : 0;
        }
    }
}

// =====================================================================
// 1) HMMA GEMM: h = F@W, bf16 3-pass split, fused s1/s2
//    pipelined: reg-prefetch A, cp.async double-buffered B
// =====================================================================
__global__ void __launch_bounds__(256) gemm_mma_kernel(const float* __restrict__ F,
                                                       const float* __restrict__ a) {
    extern __shared__ char smem[];
    const uint32_t sb = smem_u32(smem);
    const int tid  = threadIdx.x;
    const int wid  = tid >> 5;
    const int lane = tid & 31;
    const int warp_m = wid & 1;
    const int warp_n = wid >> 1;
    const int row0 = blockIdx.x * 128;

    {
        float* avec = (float*)(smem + SM_AVEC);
        avec[tid] = __ldg(a + tid);
        if (tid < 128) {
            ((float*)(smem + SM_S1B))[tid] = 0.0f;
            ((float*)(smem + SM_S2B))[tid] = 0.0f;
        }
    }

    float acc[4][4][4];
    #pragma unroll
    for (int mt = 0; mt < 4; ++mt)
        #pragma unroll
        for (int nt = 0; nt < 4; ++nt)
            #pragma unroll
            for (int j = 0; j < 4; ++j) acc[mt][nt][j] = 0.0f;

    __nv_bfloat16* sAh = (__nv_bfloat16*)(smem + SM_AH);
    __nv_bfloat16* sAl = (__nv_bfloat16*)(smem + SM_AL);

    // ---- A prefetch (registers): chunk 0
    float4 pf[8];
    #pragma unroll
    for (int it = 0; it < 8; ++it) {
        const int lin = tid + 256 * it;
        const int r = lin >> 4, j = lin & 15;
        pf[it] = make_float4(0.f, 0.f, 0.f, 0.f);
        if (row0 + r < N_NODES)
            pf[it] = *reinterpret_cast<const float4*>(
                         F + (size_t)(row0 + r) * IN_DIM + 0 * 64 + j * 4);
    }
    // ---- B cp.async: chunk 0 -> buf 0  (8 x 16B per thread: 4 hi + 4 lo)
    {
        const uint32_t bbase = sb + SM_B0;
        #pragma unroll
        for (int it = 0; it < 4; ++it) {
            const int lin = tid + 256 * it;        // 1024 uint4s
            const int n = lin >> 3, j = lin & 7;
            cp16(bbase + (uint32_t)(n * PAD + j * 8) * 2,
                 &g_WTh[n * IN_DIM + 0 * 64 + j * 8]);
            cp16(bbase + B_LO_OFF + (uint32_t)(n * PAD + j * 8) * 2,
                 &g_WTl[n * IN_DIM + 0 * 64 + j * 8]);
        }
        CP_COMMIT();
    }

    for (int c = 0; c < 4; ++c) {
        __syncthreads();   // A smem free from previous compute

        // store prefetched A chunk with hi/lo conversion
        #pragma unroll
        for (int it = 0; it < 8; ++it) {
            const int lin = tid + 256 * it;
            const int r = lin >> 4, j = lin & 15;
            const float4 v = pf[it];
            __nv_bfloat162 h01 = __floats2bfloat162_rn(v.x, v.y);
            __nv_bfloat162 h23 = __floats2bfloat162_rn(v.z, v.w);
            __nv_bfloat162 l01 = __floats2bfloat162_rn(v.x - __bfloat162float(h01.x),
                                                       v.y - __bfloat162float(h01.y));
            __nv_bfloat162 l23 = __floats2bfloat162_rn(v.z - __bfloat162float(h23.x),
                                                       v.w - __bfloat162float(h23.y));
            *(uint2*)&sAh[r * PAD + j * 4] = make_uint2(*(uint32_t*)&h01, *(uint32_t*)&h23);
            *(uint2*)&sAl[r * PAD + j * 4] = make_uint2(*(uint32_t*)&l01, *(uint32_t*)&l23);
        }

        // kick off next B chunk into alternate buffer
        if (c < 3) {
            const uint32_t bbase = sb + SM_B0 + ((c + 1) & 1) * B_BUF_STRIDE;
            #pragma unroll
            for (int it = 0; it < 4; ++it) {
                const int lin = tid + 256 * it;
                const int n = lin >> 3, j = lin & 7;
                cp16(bbase + (uint32_t)(n * PAD + j * 8) * 2,
                     &g_WTh[n * IN_DIM + (c + 1) * 64 + j * 8]);
                cp16(bbase + B_LO_OFF + (uint32_t)(n * PAD + j * 8) * 2,
                     &g_WTl[n * IN_DIM + (c + 1) * 64 + j * 8]);
            }
            CP_COMMIT();
            CP_WAIT1();          // chunk c's group complete
        } else {
            CP_WAIT0();
        }
        __syncthreads();

        // prefetch next A chunk (LDGs overlap the MMA section below)
        if (c < 3) {
            #pragma unroll
            for (int it = 0; it < 8; ++it) {
                const int lin = tid + 256 * it;
                const int r = lin >> 4, j = lin & 15;
                pf[it] = make_float4(0.f, 0.f, 0.f, 0.f);
                if (row0 + r < N_NODES)
                    pf[it] = *reinterpret_cast<const float4*>(
                                 F + (size_t)(row0 + r) * IN_DIM + (c + 1) * 64 + j * 4);
            }
        }

        // ---- compute chunk c
        const uint32_t bh_off = SM_B0 + (c & 1) * B_BUF_STRIDE;
        const uint32_t bl_off = bh_off + B_LO_OFF;
        const int rs = lane & 7, q = lane >> 3;
        #pragma unroll
        for (int ks = 0; ks < 4; ++ks) {
            const int k0 = ks * 16;
            uint32_t ah[4][4], al[4][4];
            #pragma unroll
            for (int mt = 0; mt < 4; ++mt) {
                const int arow = warp_m * 64 + mt * 16 + rs + (q & 1) * 8;
                const int acol = k0 + (q >> 1) * 8;
                const uint32_t off = (uint32_t)(arow * PAD + acol) * 2;
                ldmx4(ah[mt], sb + SM_AH + off);
                ldmx4(al[mt], sb + SM_AL + off);
            }
            uint32_t bh[2][4], bl[2][4];
            #pragma unroll
            for (int np = 0; np < 2; ++np) {
                const int brow = warp_n * 32 + np * 16 + rs + (q >> 1) * 8;
                const int bcol = k0 + (q & 1) * 8;
                const uint32_t off = (uint32_t)(brow * PAD + bcol) * 2;
                ldmx4(bh[np], sb + bh_off + off);
                ldmx4(bl[np], sb + bl_off + off);
            }
            #pragma unroll
            for (int mt = 0; mt < 4; ++mt)
                #pragma unroll
                for (int nt = 0; nt < 4; ++nt) {
                    const uint32_t* bhp = &bh[nt >> 1][(nt & 1) * 2];
                    const uint32_t* blp = &bl[nt >> 1][(nt & 1) * 2];
                    mma16816(acc[mt][nt], ah[mt], bhp);   // Ah*Bh
                    mma16816(acc[mt][nt], ah[mt], blp);   // Ah*Bl
                    mma16816(acc[mt][nt], al[mt], bhp);   // Al*Bh
                }
        }
    }

    // epilogue: write h, fuse s1/s2
    const float* avec = (const float*)(smem + SM_AVEC);
    float* s1b = (float*)(smem + SM_S1B);
    float* s2b = (float*)(smem + SM_S2B);
    const int tg = lane & 3, gid = lane >> 2;

    #pragma unroll
    for (int mt = 0; mt < 4; ++mt)
        #pragma unroll
        for (int half = 0; half < 2; ++half) {
            const int rloc = warp_m * 64 + mt * 16 + half * 8 + gid;
            const int row  = row0 + rloc;
            float s1p = 0.f, s2p = 0.f;
            #pragma unroll
            for (int nt = 0; nt < 4; ++nt) {
                const float vx = acc[mt][nt][half * 2 + 0];
                const float vy = acc[mt][nt][half * 2 + 1];
                const int col = warp_n * 32 + nt * 8 + tg * 2;
                if (row < N_NODES)
                    *reinterpret_cast<float2*>(g_h + (size_t)row * OUT_DIM + col) =
                        make_float2(vx, vy);
                s1p += vx * avec[col]       + vy * avec[col + 1];
                s2p += vx * avec[128 + col] + vy * avec[128 + col + 1];
            }
            s1p += __shfl_xor_sync(0xffffffffu, s1p, 1);
            s1p += __shfl_xor_sync(0xffffffffu, s1p, 2);
            s2p += __shfl_xor_sync(0xffffffffu, s2p, 1);
            s2p += __shfl_xor_sync(0xffffffffu, s2p, 2);
            if (tg == 0) {
                atomicAdd(&s1b[rloc], s1p);
                atomicAdd(&s2b[rloc], s2p);
            }
        }
    __syncthreads();
    if (tid < 128 && row0 + tid < N_NODES) {
        g_s1[row0 + tid] = s1b[tid];
        g_s2[row0 + tid] = s2b[tid];
    }
}

// =====================================================================
// 2) per-edge bucketing: 4 edges/thread, batched for MLP
//    (runs in a side stream, overlapped with the GEMM)
// =====================================================================
__global__ void __launch_bounds__(256) edge_kernel(const void* __restrict__ tgt_raw) {
    const int base = blockIdx.x * 256 + threadIdx.x;   // grid 256 -> 65536 threads
    const int is64 = g_idx64;
    int t[4];
    #pragma unroll
    for (int u = 0; u < 4; ++u) {
        const int i = base + u * 65536;
        t[u] = is64 ? (int)((const long long*)tgt_raw)[i]
                    : ((const int*)tgt_raw)[i];
    }
    int p[4];
    #pragma unroll
    for (int u = 0; u < 4; ++u) p[u] = atomicAdd(&g_cnt[t[u]], 1);
    #pragma unroll
    for (int u = 0; u < 4; ++u)
        if (p[u] < CAP) g_bucket[t[u] * CAP + p[u]] = base + u * 65536;
}

// =====================================================================
// 3) per-row: score + dedup (last write wins) + softmax + gather + ELU
//    k==0 fallback computes the column mean in-block (prob ~1e-24)
// =====================================================================
__global__ void __launch_bounds__(128) row_kernel(const void* __restrict__ adj_raw,
                                                  float* __restrict__ out) {
    const int t   = blockIdx.x;
    const int tid = threadIdx.x;

    __shared__ int   sdst[CAP];
    __shared__ float se[CAP];
    __shared__ int   sidx[CAP];
    __shared__ float red[128];

    const int k = min(g_cnt[t], CAP);

    if (k == 0) {
        // empty row: softmax over all -9e15 is uniform -> column mean of h.
        // Essentially unreachable (P ~ 1e-24) but kept for correctness.
        float s = 0.f;
        for (int row = 0; row < N_NODES; ++row)
            s += g_h[(size_t)row * OUT_DIM + tid];
        float v = s * (1.0f / (float)N_NODES);
        out[(size_t)t * OUT_DIM + tid] = (v > 0.f) ? v : expm1f(v);
        return;
    }

    const int is64 = g_idx64;
    for (int i = tid; i < k; i += 128) {
        const int e = g_bucket[t * CAP + i];
        int src, dst;
        if (is64) {
            src = (int)((const long long*)adj_raw)[e];
            dst = (int)((const long long*)adj_raw)[N_EDGES + e];
        } else {
            src = ((const int*)adj_raw)[e];
            dst = ((const int*)adj_raw)[N_EDGES + e];
        }
        sidx[i] = e;
        sdst[i] = dst;
        float sc = g_s1[src] + g_s2[dst];
        se[i] = (sc > 0.f) ? sc : LRELU_ALPHA * sc;
    }
    __syncthreads();

    // dedup: cell (t,dst) keeps the highest original edge index
    for (int i = tid; i < k; i += 128) {
        const int d = sdst[i], my = sidx[i];
        bool dead = false;
        for (int j = 0; j < k; ++j)
            if (sdst[j] == d && sidx[j] > my) { dead = true; break; }
        if (dead) se[i] = -3.0e38f;
    }
    __syncthreads();

    float m = -3.0e38f;
    for (int i = tid; i < k; i += 128) m = fmaxf(m, se[i]);
    red[tid] = m;
    __syncthreads();
    #pragma unroll
    for (int s = 64; s; s >>= 1) { if (tid < s) red[tid] = fmaxf(red[tid], red[tid + s]); __syncthreads(); }
    m = red[0];
    __syncthreads();

    float ssum = 0.f;
    for (int i = tid; i < k; i += 128) { float w = __expf(se[i] - m); se[i] = w; ssum += w; }
    __syncthreads();
    red[tid] = ssum;
    __syncthreads();
    #pragma unroll
    for (int s = 64; s; s >>= 1) { if (tid < s) red[tid] += red[tid + s]; __syncthreads(); }
    const float inv = 1.0f / red[0];
    __syncthreads();

    float acc = 0.f;
    #pragma unroll 4
    for (int i = 0; i < k; ++i)
        acc += se[i] * g_h[(size_t)sdst[i] * OUT_DIM + tid];

    const float v = acc * inv;
    out[(size_t)t * OUT_DIM + tid] = (v > 0.f) ? v : expm1f(v);
}

// =====================================================================
extern "C" void kernel_launch(void* const* d_in, const int* in_sizes, int n_in,
                              void* d_out, int out_size) {
    const float* F   = (const float*)d_in[0];
    const void*  adj = d_in[1];
    const void*  tgt = d_in[2];
    const float* W   = (const float*)d_in[3];
    const float* a   = (const float*)d_in[4];
    float* out = (float*)d_out;

    static cudaStream_t s2 = nullptr;
    static cudaEvent_t  ev_fork = nullptr, ev_join = nullptr;
    static int inited = 0;
    if (!inited) {
        cudaFuncSetAttribute(gemm_mma_kernel,
                             cudaFuncAttributeMaxDynamicSharedMemorySize, SMEM_TOTAL);
        cudaStreamCreateWithFlags(&s2, cudaStreamNonBlocking);
        cudaEventCreateWithFlags(&ev_fork, cudaEventDisableTiming);
        cudaEventCreateWithFlags(&ev_join, cudaEventDisableTiming);
        inited = 1;
    }

    // main stream: prep -> gemm ; side stream: edge (bucketing)
    prep_kernel<<<145, 256>>>(W, adj);
    cudaEventRecord(ev_fork, 0);
    cudaStreamWaitEvent(s2, ev_fork, 0);

    gemm_mma_kernel<<<(N_NODES + 127) / 128, 256, SMEM_TOTAL>>>(F, a);
    edge_kernel<<<256, 256, 0, s2>>>(tgt);
    cudaEventRecord(ev_join, s2);

    cudaStreamWaitEvent(0, ev_join, 0);
    row_kernel<<<T_ROWS, 128>>>(adj, out);
}

// round 6
// speedup vs baseline: 2.7048x; 1.1632x over previous
#include <cuda_runtime.h>
#include <cuda_bf16.h>
#include <math.h>
#include <stdint.h>

#define N_NODES 50000
#define IN_DIM  256
#define OUT_DIM 128
#define T_ROWS  4096
#define N_EDGES 262144
#define CAP     256
#define LRELU_ALPHA 0.2f
#define PAD 72   // bf16 elements per smem row (144B): conflict-free ldmatrix
#define HSZ 512  // dedup hash table slots (power of 2)

// ---- scratch (static __device__ globals: allocation-free) ----
__device__ float g_h[(size_t)N_NODES * OUT_DIM];   // 25.6 MB
__device__ float g_s1[N_NODES];
__device__ float g_s2[N_NODES];
__device__ int   g_cnt[T_ROWS];
__device__ int   g_bucket[T_ROWS * CAP];
__device__ int   g_idx64;
// W^T pre-split: [128 n][256 k] bf16 hi/lo
__device__ __nv_bfloat16 g_WTh[OUT_DIM * IN_DIM];
__device__ __nv_bfloat16 g_WTl[OUT_DIM * IN_DIM];

// ---------------- helpers ----------------
__device__ __forceinline__ uint32_t smem_u32(const void* p) {
    uint32_t a;
    asm("{ .reg .u64 t; cvta.to.shared.u64 t, %1; cvt.u32.u64 %0, t; }" : "=r"(a) : "l"(p));
    return a;
}
__device__ __forceinline__ void ldmx4(uint32_t (&r)[4], uint32_t addr) {
    asm volatile("ldmatrix.sync.aligned.m8n8.x4.shared.b16 {%0,%1,%2,%3}, [%4];"
                 : "=r"(r[0]), "=r"(r[1]), "=r"(r[2]), "=r"(r[3]) : "r"(addr));
}
__device__ __forceinline__ void mma16816(float (&c)[4], const uint32_t (&a)[4],
                                         const uint32_t* b) {
    asm volatile("mma.sync.aligned.m16n8k16.row.col.f32.bf16.bf16.f32 "
                 "{%0,%1,%2,%3}, {%4,%5,%6,%7}, {%8,%9}, {%0,%1,%2,%3};"
                 : "+f"(c[0]), "+f"(c[1]), "+f"(c[2]), "+f"(c[3])
                 : "r"(a[0]), "r"(a[1]), "r"(a[2]), "r"(a[3]), "r"(b[0]), "r"(b[1]));
}
__device__ __forceinline__ void cp16(uint32_t dst, const void* src) {
    asm volatile("cp.async.cg.shared.global [%0], [%1], 16;" :: "r"(dst), "l"(src) : "memory");
}
#define CP_COMMIT() asm volatile("cp.async.commit_group;" ::: "memory")
#define CP_WAIT1()  asm volatile("cp.async.wait_group 1;" ::: "memory")
#define CP_WAIT0()  asm volatile("cp.async.wait_group 0;" ::: "memory")

// SMEM layout (bytes) for gemm kernel
#define SM_AH    0                     // 18432
#define SM_AL    18432                 // 18432
#define SM_B0    36864                 // buf0: hi 18432 + lo 18432
#define SM_B1    73728                 // buf1: hi 18432 + lo 18432
#define SM_AVEC  110592                // 256 floats
#define SM_S1B   111616                // 128 floats
#define SM_S2B   112128
#define SMEM_TOTAL 112640
#define B_BUF_STRIDE 36864
#define B_LO_OFF 18432

// =====================================================================
// 0) prep: W split + counters + dtype sniff (one launch)
// =====================================================================
__global__ void prep_kernel(const float* __restrict__ W,
                            const void* __restrict__ adj_raw) {
    const int b = blockIdx.x;
    if (b < 128) {
        const int i = b * 256 + threadIdx.x;    // 0..32767
        const int k = i >> 7, n = i & 127;
        const float v = W[i];
        __nv_bfloat16 h = __float2bfloat16(v);
        __nv_bfloat16 l = __float2bfloat16(v - __bfloat162float(h));
        g_WTh[n * IN_DIM + k] = h;
        g_WTl[n * IN_DIM + k] = l;
    } else {
        const int i = (b - 128) * 256 + threadIdx.x;  // 0..4351
        if (i < T_ROWS) g_cnt[i] = 0;
        if (b == 144) {
            const int* w = (const int*)adj_raw;
            int bad = 0;
            for (int j = threadIdx.x * 2 + 1; j < 8192; j += 512)
                if (w[j] != 0) bad = 1;
            __shared__ int sbad;
            if (threadIdx.x == 0) sbad = 0;
            __syncthreads();
            if (bad) atomicOr(&sbad, 1);
            __syncthreads();
            if (threadIdx.x == 0) g_idx64 = (sbad == 0) ? 1 : 0;
        }
    }
}

// =====================================================================
// 1) HMMA GEMM: h = F@W, bf16 3-pass split, fused s1/s2
// =====================================================================
__global__ void __launch_bounds__(256) gemm_mma_kernel(const float* __restrict__ F,
                                                       const float* __restrict__ a) {
    extern __shared__ char smem[];
    const uint32_t sb = smem_u32(smem);
    const int tid  = threadIdx.x;
    const int wid  = tid >> 5;
    const int lane = tid & 31;
    const int warp_m = wid & 1;
    const int warp_n = wid >> 1;
    const int row0 = blockIdx.x * 128;

    {
        float* avec = (float*)(smem + SM_AVEC);
        avec[tid] = __ldg(a + tid);
        if (tid < 128) {
            ((float*)(smem + SM_S1B))[tid] = 0.0f;
            ((float*)(smem + SM_S2B))[tid] = 0.0f;
        }
    }

    float acc[4][4][4];
    #pragma unroll
    for (int mt = 0; mt < 4; ++mt)
        #pragma unroll
        for (int nt = 0; nt < 4; ++nt)
            #pragma unroll
            for (int j = 0; j < 4; ++j) acc[mt][nt][j] = 0.0f;

    __nv_bfloat16* sAh = (__nv_bfloat16*)(smem + SM_AH);
    __nv_bfloat16* sAl = (__nv_bfloat16*)(smem + SM_AL);

    float4 pf[8];
    #pragma unroll
    for (int it = 0; it < 8; ++it) {
        const int lin = tid + 256 * it;
        const int r = lin >> 4, j = lin & 15;
        pf[it] = make_float4(0.f, 0.f, 0.f, 0.f);
        if (row0 + r < N_NODES)
            pf[it] = *reinterpret_cast<const float4*>(
                         F + (size_t)(row0 + r) * IN_DIM + 0 * 64 + j * 4);
    }
    {
        const uint32_t bbase = sb + SM_B0;
        #pragma unroll
        for (int it = 0; it < 4; ++it) {
            const int lin = tid + 256 * it;
            const int n = lin >> 3, j = lin & 7;
            cp16(bbase + (uint32_t)(n * PAD + j * 8) * 2,
                 &g_WTh[n * IN_DIM + 0 * 64 + j * 8]);
            cp16(bbase + B_LO_OFF + (uint32_t)(n * PAD + j * 8) * 2,
                 &g_WTl[n * IN_DIM + 0 * 64 + j * 8]);
        }
        CP_COMMIT();
    }

    for (int c = 0; c < 4; ++c) {
        __syncthreads();

        #pragma unroll
        for (int it = 0; it < 8; ++it) {
            const int lin = tid + 256 * it;
            const int r = lin >> 4, j = lin & 15;
            const float4 v = pf[it];
            __nv_bfloat162 h01 = __floats2bfloat162_rn(v.x, v.y);
            __nv_bfloat162 h23 = __floats2bfloat162_rn(v.z, v.w);
            __nv_bfloat162 l01 = __floats2bfloat162_rn(v.x - __bfloat162float(h01.x),
                                                       v.y - __bfloat162float(h01.y));
            __nv_bfloat162 l23 = __floats2bfloat162_rn(v.z - __bfloat162float(h23.x),
                                                       v.w - __bfloat162float(h23.y));
            *(uint2*)&sAh[r * PAD + j * 4] = make_uint2(*(uint32_t*)&h01, *(uint32_t*)&h23);
            *(uint2*)&sAl[r * PAD + j * 4] = make_uint2(*(uint32_t*)&l01, *(uint32_t*)&l23);
        }

        if (c < 3) {
            const uint32_t bbase = sb + SM_B0 + ((c + 1) & 1) * B_BUF_STRIDE;
            #pragma unroll
            for (int it = 0; it < 4; ++it) {
                const int lin = tid + 256 * it;
                const int n = lin >> 3, j = lin & 7;
                cp16(bbase + (uint32_t)(n * PAD + j * 8) * 2,
                     &g_WTh[n * IN_DIM + (c + 1) * 64 + j * 8]);
                cp16(bbase + B_LO_OFF + (uint32_t)(n * PAD + j * 8) * 2,
                     &g_WTl[n * IN_DIM + (c + 1) * 64 + j * 8]);
            }
            CP_COMMIT();
            CP_WAIT1();
        } else {
            CP_WAIT0();
        }
        __syncthreads();

        if (c < 3) {
            #pragma unroll
            for (int it = 0; it < 8; ++it) {
                const int lin = tid + 256 * it;
                const int r = lin >> 4, j = lin & 15;
                pf[it] = make_float4(0.f, 0.f, 0.f, 0.f);
                if (row0 + r < N_NODES)
                    pf[it] = *reinterpret_cast<const float4*>(
                                 F + (size_t)(row0 + r) * IN_DIM + (c + 1) * 64 + j * 4);
            }
        }

        const uint32_t bh_off = SM_B0 + (c & 1) * B_BUF_STRIDE;
        const uint32_t bl_off = bh_off + B_LO_OFF;
        const int rs = lane & 7, q = lane >> 3;
        #pragma unroll
        for (int ks = 0; ks < 4; ++ks) {
            const int k0 = ks * 16;
            uint32_t ah[4][4], al[4][4];
            #pragma unroll
            for (int mt = 0; mt < 4; ++mt) {
                const int arow = warp_m * 64 + mt * 16 + rs + (q & 1) * 8;
                const int acol = k0 + (q >> 1) * 8;
                const uint32_t off = (uint32_t)(arow * PAD + acol) * 2;
                ldmx4(ah[mt], sb + SM_AH + off);
                ldmx4(al[mt], sb + SM_AL + off);
            }
            uint32_t bh[2][4], bl[2][4];
            #pragma unroll
            for (int np = 0; np < 2; ++np) {
                const int brow = warp_n * 32 + np * 16 + rs + (q >> 1) * 8;
                const int bcol = k0 + (q & 1) * 8;
                const uint32_t off = (uint32_t)(brow * PAD + bcol) * 2;
                ldmx4(bh[np], sb + bh_off + off);
                ldmx4(bl[np], sb + bl_off + off);
            }
            #pragma unroll
            for (int mt = 0; mt < 4; ++mt)
                #pragma unroll
                for (int nt = 0; nt < 4; ++nt) {
                    const uint32_t* bhp = &bh[nt >> 1][(nt & 1) * 2];
                    const uint32_t* blp = &bl[nt >> 1][(nt & 1) * 2];
                    mma16816(acc[mt][nt], ah[mt], bhp);
                    mma16816(acc[mt][nt], ah[mt], blp);
                    mma16816(acc[mt][nt], al[mt], bhp);
                }
        }
    }

    const float* avec = (const float*)(smem + SM_AVEC);
    float* s1b = (float*)(smem + SM_S1B);
    float* s2b = (float*)(smem + SM_S2B);
    const int tg = lane & 3, gid = lane >> 2;

    #pragma unroll
    for (int mt = 0; mt < 4; ++mt)
        #pragma unroll
        for (int half = 0; half < 2; ++half) {
            const int rloc = warp_m * 64 + mt * 16 + half * 8 + gid;
            const int row  = row0 + rloc;
            float s1p = 0.f, s2p = 0.f;
            #pragma unroll
            for (int nt = 0; nt < 4; ++nt) {
                const float vx = acc[mt][nt][half * 2 + 0];
                const float vy = acc[mt][nt][half * 2 + 1];
                const int col = warp_n * 32 + nt * 8 + tg * 2;
                if (row < N_NODES)
                    *reinterpret_cast<float2*>(g_h + (size_t)row * OUT_DIM + col) =
                        make_float2(vx, vy);
                s1p += vx * avec[col]       + vy * avec[col + 1];
                s2p += vx * avec[128 + col] + vy * avec[128 + col + 1];
            }
            s1p += __shfl_xor_sync(0xffffffffu, s1p, 1);
            s1p += __shfl_xor_sync(0xffffffffu, s1p, 2);
            s2p += __shfl_xor_sync(0xffffffffu, s2p, 1);
            s2p += __shfl_xor_sync(0xffffffffu, s2p, 2);
            if (tg == 0) {
                atomicAdd(&s1b[rloc], s1p);
                atomicAdd(&s2b[rloc], s2p);
            }
        }
    __syncthreads();
    if (tid < 128 && row0 + tid < N_NODES) {
        g_s1[row0 + tid] = s1b[tid];
        g_s2[row0 + tid] = s2b[tid];
    }
}

// =====================================================================
// 2) per-edge bucketing: 4 edges/thread (side stream, overlaps GEMM)
// =====================================================================
__global__ void __launch_bounds__(256) edge_kernel(const void* __restrict__ tgt_raw) {
    const int base = blockIdx.x * 256 + threadIdx.x;
    const int is64 = g_idx64;
    int t[4];
    #pragma unroll
    for (int u = 0; u < 4; ++u) {
        const int i = base + u * 65536;
        t[u] = is64 ? (int)((const long long*)tgt_raw)[i]
                    : ((const int*)tgt_raw)[i];
    }
    int p[4];
    #pragma unroll
    for (int u = 0; u < 4; ++u) p[u] = atomicAdd(&g_cnt[t[u]], 1);
    #pragma unroll
    for (int u = 0; u < 4; ++u)
        if (p[u] < CAP) g_bucket[t[u] * CAP + p[u]] = base + u * 65536;
}

// =====================================================================
// 3) per-row: hash dedup (last write wins) + softmax + gather + ELU
// =====================================================================
__global__ void __launch_bounds__(128) row_kernel(const void* __restrict__ adj_raw,
                                                  float* __restrict__ out) {
    const int t    = blockIdx.x;
    const int tid  = threadIdx.x;
    const int lane = tid & 31;
    const int wrp  = tid >> 5;

    __shared__ int   sdst[CAP];
    __shared__ float se[CAP];
    __shared__ int   sidx[CAP];
    __shared__ int   sslot[CAP];
    __shared__ int   hkey[HSZ];
    __shared__ int   hval[HSZ];
    __shared__ float wmax[4];
    __shared__ float wsum[4];

    const int k = min(g_cnt[t], CAP);

    if (k == 0) {
        // empty row: uniform softmax -> column mean of h (P ~ 1e-24, kept for correctness)
        float s = 0.f;
        for (int row = 0; row < N_NODES; ++row)
            s += g_h[(size_t)row * OUT_DIM + tid];
        float v = s * (1.0f / (float)N_NODES);
        out[(size_t)t * OUT_DIM + tid] = (v > 0.f) ? v : expm1f(v);
        return;
    }

    // init hash table
    #pragma unroll
    for (int i = tid; i < HSZ; i += 128) { hkey[i] = -1; hval[i] = -1; }
    __syncthreads();

    // load edges + score + hash insert (winner = max edge index per dst)
    const int is64 = g_idx64;
    for (int i = tid; i < k; i += 128) {
        const int e = g_bucket[t * CAP + i];
        int src, dst;
        if (is64) {
            src = (int)((const long long*)adj_raw)[e];
            dst = (int)((const long long*)adj_raw)[N_EDGES + e];
        } else {
            src = ((const int*)adj_raw)[e];
            dst = ((const int*)adj_raw)[N_EDGES + e];
        }
        sidx[i] = e;
        sdst[i] = dst;
        float sc = g_s1[src] + g_s2[dst];
        se[i] = (sc > 0.f) ? sc : LRELU_ALPHA * sc;

        int h = (int)(((uint32_t)dst * 0x9E3779B1u) >> 23);   // 9 bits -> 0..511
        while (true) {
            const int cur = hkey[h];
            if (cur == dst) break;
            if (cur == -1) {
                const int old = atomicCAS(&hkey[h], -1, dst);
                if (old == -1 || old == dst) break;
            }
            h = (h + 1) & (HSZ - 1);
        }
        sslot[i] = h;
        atomicMax(&hval[h], e);
    }
    __syncthreads();

    // mark losers dead + per-thread max
    float m = -3.0e38f;
    for (int i = tid; i < k; i += 128) {
        if (hval[sslot[i]] != sidx[i]) se[i] = -3.0e38f;
        m = fmaxf(m, se[i]);
    }
    #pragma unroll
    for (int off = 16; off; off >>= 1)
        m = fmaxf(m, __shfl_xor_sync(0xffffffffu, m, off));
    if (lane == 0) wmax[wrp] = m;
    __syncthreads();
    m = fmaxf(fmaxf(wmax[0], wmax[1]), fmaxf(wmax[2], wmax[3]));

    // exp + sum
    float ssum = 0.f;
    for (int i = tid; i < k; i += 128) {
        const float w = __expf(se[i] - m);   // dead -> exactly 0
        se[i] = w;
        ssum += w;
    }
    #pragma unroll
    for (int off = 16; off; off >>= 1)
        ssum += __shfl_xor_sync(0xffffffffu, ssum, off);
    if (lane == 0) wsum[wrp] = ssum;
    __syncthreads();                          // also publishes se[] writes
    const float inv = 1.0f / (wsum[0] + wsum[1] + wsum[2] + wsum[3]);

    // weighted gather of h rows
    float acc = 0.f;
    #pragma unroll 8
    for (int i = 0; i < k; ++i)
        acc += se[i] * g_h[(size_t)sdst[i] * OUT_DIM + tid];

    const float v = acc * inv;
    out[(size_t)t * OUT_DIM + tid] = (v > 0.f) ? v : expm1f(v);
}

// =====================================================================
extern "C" void kernel_launch(void* const* d_in, const int* in_sizes, int n_in,
                              void* d_out, int out_size) {
    const float* F   = (const float*)d_in[0];
    const void*  adj = d_in[1];
    const void*  tgt = d_in[2];
    const float* W   = (const float*)d_in[3];
    const float* a   = (const float*)d_in[4];
    float* out = (float*)d_out;

    static cudaStream_t s2 = nullptr;
    static cudaEvent_t  ev_fork = nullptr, ev_join = nullptr;
    static int inited = 0;
    if (!inited) {
        cudaFuncSetAttribute(gemm_mma_kernel,
                             cudaFuncAttributeMaxDynamicSharedMemorySize, SMEM_TOTAL);
        cudaStreamCreateWithFlags(&s2, cudaStreamNonBlocking);
        cudaEventCreateWithFlags(&ev_fork, cudaEventDisableTiming);
        cudaEventCreateWithFlags(&ev_join, cudaEventDisableTiming);
        inited = 1;
    }

    // main stream: prep -> gemm ; side stream: edge (bucketing)
    prep_kernel<<<145, 256>>>(W, adj);
    cudaEventRecord(ev_fork, 0);
    cudaStreamWaitEvent(s2, ev_fork, 0);

    gemm_mma_kernel<<<(N_NODES + 127) / 128, 256, SMEM_TOTAL>>>(F, a);
    edge_kernel<<<256, 256, 0, s2>>>(tgt);
    cudaEventRecord(ev_join, s2);

    cudaStreamWaitEvent(0, ev_join, 0);
    row_kernel<<<T_ROWS, 128>>>(adj, out);
}

// round 7
// speedup vs baseline: 2.9184x; 1.0790x over previous
#include <cuda_runtime.h>
#include <cuda_bf16.h>
#include <math.h>
#include <stdint.h>

#define N_NODES 50000
#define IN_DIM  256
#define OUT_DIM 128
#define T_ROWS  4096
#define N_EDGES 262144
#define CAP     256
#define LRELU_ALPHA 0.2f
#define PAD 72   // bf16 elements per smem row (144B): conflict-free ldmatrix
#define HSZ 512  // dedup hash table slots (power of 2)

// ---- scratch (static __device__ globals: allocation-free) ----
__device__ float g_h[(size_t)N_NODES * OUT_DIM];   // 25.6 MB
__device__ float g_s1[N_NODES];
__device__ float g_s2[N_NODES];
__device__ int   g_cnt[T_ROWS];
__device__ int   g_bucket[T_ROWS * CAP];
__device__ int   g_idx64;
// W^T pre-split: [128 n][256 k] bf16 hi/lo
__device__ __nv_bfloat16 g_WTh[OUT_DIM * IN_DIM];
__device__ __nv_bfloat16 g_WTl[OUT_DIM * IN_DIM];

// ---------------- helpers ----------------
__device__ __forceinline__ uint32_t smem_u32(const void* p) {
    uint32_t a;
    asm("{ .reg .u64 t; cvta.to.shared.u64 t, %1; cvt.u32.u64 %0, t; }" : "=r"(a) : "l"(p));
    return a;
}
__device__ __forceinline__ void ldmx4(uint32_t (&r)[4], uint32_t addr) {
    asm volatile("ldmatrix.sync.aligned.m8n8.x4.shared.b16 {%0,%1,%2,%3}, [%4];"
                 : "=r"(r[0]), "=r"(r[1]), "=r"(r[2]), "=r"(r[3]) : "r"(addr));
}
__device__ __forceinline__ void mma16816(float (&c)[4], const uint32_t (&a)[4],
                                         const uint32_t* b) {
    asm volatile("mma.sync.aligned.m16n8k16.row.col.f32.bf16.bf16.f32 "
                 "{%0,%1,%2,%3}, {%4,%5,%6,%7}, {%8,%9}, {%0,%1,%2,%3};"
                 : "+f"(c[0]), "+f"(c[1]), "+f"(c[2]), "+f"(c[3])
                 : "r"(a[0]), "r"(a[1]), "r"(a[2]), "r"(a[3]), "r"(b[0]), "r"(b[1]));
}
__device__ __forceinline__ void cp16(uint32_t dst, const void* src) {
    asm volatile("cp.async.cg.shared.global [%0], [%1], 16;" :: "r"(dst), "l"(src) : "memory");
}
#define CP_COMMIT() asm volatile("cp.async.commit_group;" ::: "memory")
#define CP_WAIT1()  asm volatile("cp.async.wait_group 1;" ::: "memory")
#define CP_WAIT0()  asm volatile("cp.async.wait_group 0;" ::: "memory")

// SMEM layout (bytes) for gemm kernel
#define SM_AH    0                     // 18432
#define SM_AL    18432                 // 18432
#define SM_B0    36864                 // buf0: hi 18432 + lo 18432
#define SM_B1    73728                 // buf1: hi 18432 + lo 18432
#define SM_AVEC  110592                // 256 floats
#define SM_S1B   111616                // 128 floats
#define SM_S2B   112128
#define SMEM_TOTAL 112640
#define B_BUF_STRIDE 36864
#define B_LO_OFF 18432

// =====================================================================
// 0) prep: W split + counters + dtype sniff (one launch)
// =====================================================================
__global__ void prep_kernel(const float* __restrict__ W,
                            const void* __restrict__ adj_raw) {
    const int b = blockIdx.x;
    if (b < 128) {
        const int i = b * 256 + threadIdx.x;    // 0..32767
        const int k = i >> 7, n = i & 127;
        const float v = W[i];
        __nv_bfloat16 h = __float2bfloat16(v);
        __nv_bfloat16 l = __float2bfloat16(v - __bfloat162float(h));
        g_WTh[n * IN_DIM + k] = h;
        g_WTl[n * IN_DIM + k] = l;
    } else {
        const int i = (b - 128) * 256 + threadIdx.x;  // 0..4351
        if (i < T_ROWS) g_cnt[i] = 0;
        if (b == 144) {
            const int* w = (const int*)adj_raw;
            int bad = 0;
            for (int j = threadIdx.x * 2 + 1; j < 8192; j += 512)
                if (w[j] != 0) bad = 1;
            __shared__ int sbad;
            if (threadIdx.x == 0) sbad = 0;
            __syncthreads();
            if (bad) atomicOr(&sbad, 1);
            __syncthreads();
            if (threadIdx.x == 0) g_idx64 = (sbad == 0) ? 1 : 0;
        }
    }
}

// =====================================================================
// 1) HMMA GEMM: h = F@W, bf16 3-pass split, fused s1/s2
// =====================================================================
__global__ void __launch_bounds__(256) gemm_mma_kernel(const float* __restrict__ F,
                                                       const float* __restrict__ a) {
    extern __shared__ char smem[];
    const uint32_t sb = smem_u32(smem);
    const int tid  = threadIdx.x;
    const int wid  = tid >> 5;
    const int lane = tid & 31;
    const int warp_m = wid & 1;
    const int warp_n = wid >> 1;
    const int row0 = blockIdx.x * 128;

    {
        float* avec = (float*)(smem + SM_AVEC);
        avec[tid] = __ldg(a + tid);
        if (tid < 128) {
            ((float*)(smem + SM_S1B))[tid] = 0.0f;
            ((float*)(smem + SM_S2B))[tid] = 0.0f;
        }
    }

    float acc[4][4][4];
    #pragma unroll
    for (int mt = 0; mt < 4; ++mt)
        #pragma unroll
        for (int nt = 0; nt < 4; ++nt)
            #pragma unroll
            for (int j = 0; j < 4; ++j) acc[mt][nt][j] = 0.0f;

    __nv_bfloat16* sAh = (__nv_bfloat16*)(smem + SM_AH);
    __nv_bfloat16* sAl = (__nv_bfloat16*)(smem + SM_AL);

    float4 pf[8];
    #pragma unroll
    for (int it = 0; it < 8; ++it) {
        const int lin = tid + 256 * it;
        const int r = lin >> 4, j = lin & 15;
        pf[it] = make_float4(0.f, 0.f, 0.f, 0.f);
        if (row0 + r < N_NODES)
            pf[it] = *reinterpret_cast<const float4*>(
                         F + (size_t)(row0 + r) * IN_DIM + 0 * 64 + j * 4);
    }
    {
        const uint32_t bbase = sb + SM_B0;
        #pragma unroll
        for (int it = 0; it < 4; ++it) {
            const int lin = tid + 256 * it;
            const int n = lin >> 3, j = lin & 7;
            cp16(bbase + (uint32_t)(n * PAD + j * 8) * 2,
                 &g_WTh[n * IN_DIM + 0 * 64 + j * 8]);
            cp16(bbase + B_LO_OFF + (uint32_t)(n * PAD + j * 8) * 2,
                 &g_WTl[n * IN_DIM + 0 * 64 + j * 8]);
        }
        CP_COMMIT();
    }

    for (int c = 0; c < 4; ++c) {
        __syncthreads();

        #pragma unroll
        for (int it = 0; it < 8; ++it) {
            const int lin = tid + 256 * it;
            const int r = lin >> 4, j = lin & 15;
            const float4 v = pf[it];
            __nv_bfloat162 h01 = __floats2bfloat162_rn(v.x, v.y);
            __nv_bfloat162 h23 = __floats2bfloat162_rn(v.z, v.w);
            __nv_bfloat162 l01 = __floats2bfloat162_rn(v.x - __bfloat162float(h01.x),
                                                       v.y - __bfloat162float(h01.y));
            __nv_bfloat162 l23 = __floats2bfloat162_rn(v.z - __bfloat162float(h23.x),
                                                       v.w - __bfloat162float(h23.y));
            *(uint2*)&sAh[r * PAD + j * 4] = make_uint2(*(uint32_t*)&h01, *(uint32_t*)&h23);
            *(uint2*)&sAl[r * PAD + j * 4] = make_uint2(*(uint32_t*)&l01, *(uint32_t*)&l23);
        }

        if (c < 3) {
            const uint32_t bbase = sb + SM_B0 + ((c + 1) & 1) * B_BUF_STRIDE;
            #pragma unroll
            for (int it = 0; it < 4; ++it) {
                const int lin = tid + 256 * it;
                const int n = lin >> 3, j = lin & 7;
                cp16(bbase + (uint32_t)(n * PAD + j * 8) * 2,
                     &g_WTh[n * IN_DIM + (c + 1) * 64 + j * 8]);
                cp16(bbase + B_LO_OFF + (uint32_t)(n * PAD + j * 8) * 2,
                     &g_WTl[n * IN_DIM + (c + 1) * 64 + j * 8]);
            }
            CP_COMMIT();
            CP_WAIT1();
        } else {
            CP_WAIT0();
        }
        __syncthreads();

        if (c < 3) {
            #pragma unroll
            for (int it = 0; it < 8; ++it) {
                const int lin = tid + 256 * it;
                const int r = lin >> 4, j = lin & 15;
                pf[it] = make_float4(0.f, 0.f, 0.f, 0.f);
                if (row0 + r < N_NODES)
                    pf[it] = *reinterpret_cast<const float4*>(
                                 F + (size_t)(row0 + r) * IN_DIM + (c + 1) * 64 + j * 4);
            }
        }

        const uint32_t bh_off = SM_B0 + (c & 1) * B_BUF_STRIDE;
        const uint32_t bl_off = bh_off + B_LO_OFF;
        const int rs = lane & 7, q = lane >> 3;
        #pragma unroll
        for (int ks = 0; ks < 4; ++ks) {
            const int k0 = ks * 16;
            uint32_t ah[4][4], al[4][4];
            #pragma unroll
            for (int mt = 0; mt < 4; ++mt) {
                const int arow = warp_m * 64 + mt * 16 + rs + (q & 1) * 8;
                const int acol = k0 + (q >> 1) * 8;
                const uint32_t off = (uint32_t)(arow * PAD + acol) * 2;
                ldmx4(ah[mt], sb + SM_AH + off);
                ldmx4(al[mt], sb + SM_AL + off);
            }
            uint32_t bh[2][4], bl[2][4];
            #pragma unroll
            for (int np = 0; np < 2; ++np) {
                const int brow = warp_n * 32 + np * 16 + rs + (q >> 1) * 8;
                const int bcol = k0 + (q & 1) * 8;
                const uint32_t off = (uint32_t)(brow * PAD + bcol) * 2;
                ldmx4(bh[np], sb + bh_off + off);
                ldmx4(bl[np], sb + bl_off + off);
            }
            #pragma unroll
            for (int mt = 0; mt < 4; ++mt)
                #pragma unroll
                for (int nt = 0; nt < 4; ++nt) {
                    const uint32_t* bhp = &bh[nt >> 1][(nt & 1) * 2];
                    const uint32_t* blp = &bl[nt >> 1][(nt & 1) * 2];
                    mma16816(acc[mt][nt], ah[mt], bhp);
                    mma16816(acc[mt][nt], ah[mt], blp);
                    mma16816(acc[mt][nt], al[mt], bhp);
                }
        }
    }

    const float* avec = (const float*)(smem + SM_AVEC);
    float* s1b = (float*)(smem + SM_S1B);
    float* s2b = (float*)(smem + SM_S2B);
    const int tg = lane & 3, gid = lane >> 2;

    #pragma unroll
    for (int mt = 0; mt < 4; ++mt)
        #pragma unroll
        for (int half = 0; half < 2; ++half) {
            const int rloc = warp_m * 64 + mt * 16 + half * 8 + gid;
            const int row  = row0 + rloc;
            float s1p = 0.f, s2p = 0.f;
            #pragma unroll
            for (int nt = 0; nt < 4; ++nt) {
                const float vx = acc[mt][nt][half * 2 + 0];
                const float vy = acc[mt][nt][half * 2 + 1];
                const int col = warp_n * 32 + nt * 8 + tg * 2;
                if (row < N_NODES)
                    *reinterpret_cast<float2*>(g_h + (size_t)row * OUT_DIM + col) =
                        make_float2(vx, vy);
                s1p += vx * avec[col]       + vy * avec[col + 1];
                s2p += vx * avec[128 + col] + vy * avec[128 + col + 1];
            }
            s1p += __shfl_xor_sync(0xffffffffu, s1p, 1);
            s1p += __shfl_xor_sync(0xffffffffu, s1p, 2);
            s2p += __shfl_xor_sync(0xffffffffu, s2p, 1);
            s2p += __shfl_xor_sync(0xffffffffu, s2p, 2);
            if (tg == 0) {
                atomicAdd(&s1b[rloc], s1p);
                atomicAdd(&s2b[rloc], s2p);
            }
        }
    __syncthreads();
    if (tid < 128 && row0 + tid < N_NODES) {
        g_s1[row0 + tid] = s1b[tid];
        g_s2[row0 + tid] = s2b[tid];
    }
}

// =====================================================================
// 2) per-edge bucketing: 4 edges/thread (side stream, overlaps GEMM)
// =====================================================================
__global__ void __launch_bounds__(256) edge_kernel(const void* __restrict__ tgt_raw) {
    const int base = blockIdx.x * 256 + threadIdx.x;
    const int is64 = g_idx64;
    int t[4];
    #pragma unroll
    for (int u = 0; u < 4; ++u) {
        const int i = base + u * 65536;
        t[u] = is64 ? (int)((const long long*)tgt_raw)[i]
                    : ((const int*)tgt_raw)[i];
    }
    int p[4];
    #pragma unroll
    for (int u = 0; u < 4; ++u) p[u] = atomicAdd(&g_cnt[t[u]], 1);
    #pragma unroll
    for (int u = 0; u < 4; ++u)
        if (p[u] < CAP) g_bucket[t[u] * CAP + p[u]] = base + u * 65536;
}

// =====================================================================
// 3) per-row: hash dedup (last write wins) + softmax + float4 gather + ELU
// =====================================================================
__global__ void __launch_bounds__(128) row_kernel(const void* __restrict__ adj_raw,
                                                  float* __restrict__ out) {
    const int t    = blockIdx.x;
    const int tid  = threadIdx.x;
    const int lane = tid & 31;
    const int wrp  = tid >> 5;

    __shared__ int   soff[CAP];       // dst * OUT_DIM (word offset into g_h)
    __shared__ float se[CAP];
    __shared__ int   sidx[CAP];
    __shared__ int   sslot[CAP];
    __shared__ int   hkey[HSZ];
    __shared__ int   hval[HSZ];
    __shared__ float wred[4];
    __shared__ float racc[4][OUT_DIM]; // per-warp gather partials

    const int k = min(g_cnt[t], CAP);

    if (k == 0) {
        // empty row: uniform softmax -> column mean of h (P ~ 1e-24, kept for correctness)
        float s = 0.f;
        for (int row = 0; row < N_NODES; ++row)
            s += g_h[(size_t)row * OUT_DIM + tid];
        float v = s * (1.0f / (float)N_NODES);
        out[(size_t)t * OUT_DIM + tid] = (v > 0.f) ? v : expm1f(v);
        return;
    }

    // init hash table
    #pragma unroll
    for (int i = tid; i < HSZ; i += 128) { hkey[i] = -1; hval[i] = -1; }
    __syncthreads();

    // load edges + score + hash insert (winner = max edge index per dst)
    const int is64 = g_idx64;
    for (int i = tid; i < k; i += 128) {
        const int e = g_bucket[t * CAP + i];
        int src, dst;
        if (is64) {
            src = (int)((const long long*)adj_raw)[e];
            dst = (int)((const long long*)adj_raw)[N_EDGES + e];
        } else {
            src = ((const int*)adj_raw)[e];
            dst = ((const int*)adj_raw)[N_EDGES + e];
        }
        sidx[i] = e;
        soff[i] = dst * OUT_DIM;
        float sc = g_s1[src] + g_s2[dst];
        se[i] = (sc > 0.f) ? sc : LRELU_ALPHA * sc;

        int h = (int)(((uint32_t)dst * 0x9E3779B1u) >> 23);   // 9 bits -> 0..511
        while (true) {
            const int cur = hkey[h];
            if (cur == dst) break;
            if (cur == -1) {
                const int old = atomicCAS(&hkey[h], -1, dst);
                if (old == -1 || old == dst) break;
            }
            h = (h + 1) & (HSZ - 1);
        }
        sslot[i] = h;
        atomicMax(&hval[h], e);
    }
    __syncthreads();

    // mark losers dead + per-thread max
    float m = -3.0e38f;
    for (int i = tid; i < k; i += 128) {
        if (hval[sslot[i]] != sidx[i]) se[i] = -3.0e38f;
        m = fmaxf(m, se[i]);
    }
    #pragma unroll
    for (int off = 16; off; off >>= 1)
        m = fmaxf(m, __shfl_xor_sync(0xffffffffu, m, off));
    if (lane == 0) wred[wrp] = m;
    __syncthreads();
    m = fmaxf(fmaxf(wred[0], wred[1]), fmaxf(wred[2], wred[3]));
    __syncthreads();

    // exp + sum
    float ssum = 0.f;
    for (int i = tid; i < k; i += 128) {
        const float w = __expf(se[i] - m);   // dead -> exactly 0
        se[i] = w;
        ssum += w;
    }
    #pragma unroll
    for (int off = 16; off; off >>= 1)
        ssum += __shfl_xor_sync(0xffffffffu, ssum, off);
    if (lane == 0) wred[wrp] = ssum;
    __syncthreads();                          // also publishes se[]/soff[] writes
    const float inv = 1.0f / (wred[0] + wred[1] + wred[2] + wred[3]);

    // float4 gather: warp w takes edges w, w+4, ...; lane covers cols 4l..4l+3
    float4 acc = make_float4(0.f, 0.f, 0.f, 0.f);
    const int colw = lane * 4;
    for (int i = wrp; i < k; i += 4) {
        const float w = se[i];
        const float4 hv = *reinterpret_cast<const float4*>(g_h + soff[i] + colw);
        acc.x += w * hv.x;
        acc.y += w * hv.y;
        acc.z += w * hv.z;
        acc.w += w * hv.w;
    }
    *reinterpret_cast<float4*>(&racc[wrp][colw]) = acc;
    __syncthreads();

    const float v = (racc[0][tid] + racc[1][tid] + racc[2][tid] + racc[3][tid]) * inv;
    out[(size_t)t * OUT_DIM + tid] = (v > 0.f) ? v : expm1f(v);
}

// =====================================================================
extern "C" void kernel_launch(void* const* d_in, const int* in_sizes, int n_in,
                              void* d_out, int out_size) {
    const float* F   = (const float*)d_in[0];
    const void*  adj = d_in[1];
    const void*  tgt = d_in[2];
    const float* W   = (const float*)d_in[3];
    const float* a   = (const float*)d_in[4];
    float* out = (float*)d_out;

    static cudaStream_t s2 = nullptr;
    static cudaEvent_t  ev_fork = nullptr, ev_join = nullptr;
    static int inited = 0;
    if (!inited) {
        cudaFuncSetAttribute(gemm_mma_kernel,
                             cudaFuncAttributeMaxDynamicSharedMemorySize, SMEM_TOTAL);
        cudaStreamCreateWithFlags(&s2, cudaStreamNonBlocking);
        cudaEventCreateWithFlags(&ev_fork, cudaEventDisableTiming);
        cudaEventCreateWithFlags(&ev_join, cudaEventDisableTiming);
        inited = 1;
    }

    // main stream: prep -> gemm ; side stream: edge (bucketing)
    prep_kernel<<<145, 256>>>(W, adj);
    cudaEventRecord(ev_fork, 0);
    cudaStreamWaitEvent(s2, ev_fork, 0);

    gemm_mma_kernel<<<(N_NODES + 127) / 128, 256, SMEM_TOTAL>>>(F, a);
    edge_kernel<<<256, 256, 0, s2>>>(tgt);
    cudaEventRecord(ev_join, s2);

    cudaStreamWaitEvent(0, ev_join, 0);
    row_kernel<<<T_ROWS, 128>>>(adj, out);
}